// round 12
// baseline (speedup 1.0000x reference)
#include <cuda_runtime.h>
#include <cuda_bf16.h>
#include <cstdint>

// ---------------- problem constants ----------------
#define BS   6
#define NQ   4096
#define EMB  256
#define NH   8
#define LTOT 19560            // 92*160 + 46*80 + 23*40 + 12*20
#define MQ   (BS * NQ)        // 24576
#define MV   (BS * LTOT)      // 117360
#define KDIM 256

// ---------------- scratch (device globals; no cudaMalloc allowed) ----------
__device__ float g_v  [(size_t)MV * EMB];
__device__ float g_qo [(size_t)MQ * 768];    // [attn 256 | off 512] per row
__device__ float g_tmp[(size_t)MQ * EMB];
__device__ float g_bqo[768];                 // fused bias [b_attn | b_off]

// transposed + hi/lo split weights, rows = output col n, 256 k each
// layout: [val 256 | attn 256 | off 512 | out 256] = 1280 rows
#define WT_VAL  0
#define WT_QRY  256
#define WT_OUT  1024
__device__ __align__(128) __nv_bfloat16 g_wt_hi[1280 * 256];
__device__ __align__(128) __nv_bfloat16 g_wt_lo[1280 * 256];

__constant__ int   cHL[4] = {92, 46, 23, 12};
__constant__ int   cWL[4] = {160, 80, 40, 20};
__constant__ int   cST[4] = {0, 14720, 18400, 19320};
__constant__ float cIW[4] = {1.f/160.f, 1.f/80.f, 1.f/40.f, 1.f/20.f};
__constant__ float cIH[4] = {1.f/92.f,  1.f/46.f, 1.f/23.f, 1.f/12.f};

// ---------------- helpers ---------------------------------------------------
__device__ __forceinline__ uint32_t smem_u32(const void* p) {
    uint32_t a;
    asm("{ .reg .u64 t; cvta.to.shared.u64 t, %1; cvt.u32.u64 %0, t; }"
        : "=r"(a) : "l"(p));
    return a;
}
__device__ __forceinline__ void ldsm_x4(uint32_t* r, uint32_t addr) {
    asm volatile("ldmatrix.sync.aligned.m8n8.x4.shared.b16 {%0,%1,%2,%3}, [%4];"
                 : "=r"(r[0]), "=r"(r[1]), "=r"(r[2]), "=r"(r[3]) : "r"(addr));
}
__device__ __forceinline__ void mma_bf16(float* c, const uint32_t* a,
                                         const uint32_t* b) {
    asm volatile(
        "mma.sync.aligned.m16n8k16.row.col.f32.bf16.bf16.f32 "
        "{%0,%1,%2,%3}, {%4,%5,%6,%7}, {%8,%9}, {%0,%1,%2,%3};"
        : "+f"(c[0]), "+f"(c[1]), "+f"(c[2]), "+f"(c[3])
        : "r"(a[0]), "r"(a[1]), "r"(a[2]), "r"(a[3]), "r"(b[0]), "r"(b[1]));
}
__device__ __forceinline__ void cp16(uint32_t dst, const void* src) {
    asm volatile("cp.async.cg.shared.global [%0], [%1], 16;"
                 :: "r"(dst), "l"(src) : "memory");
}
#define CP_COMMIT() asm volatile("cp.async.commit_group;" ::: "memory")
#define CP_WAIT(n)  asm volatile("cp.async.wait_group " #n ";" ::: "memory")

// ---------------- weight prep: transpose + bf16 hi/lo split ---------------
__global__ void prep_weights(const float* __restrict__ Wv,
                             const float* __restrict__ Wa,
                             const float* __restrict__ Wf,
                             const float* __restrict__ Wo,
                             const float* __restrict__ ba,
                             const float* __restrict__ bf)
{
    const int n = blockIdx.x;
    const int k = threadIdx.x;
    if (n == 0) g_bqo[k]       = ba[k];
    if (n == 1) g_bqo[256 + k] = bf[k];
    if (n == 2) g_bqo[512 + k] = bf[256 + k];
    const float* W; int N, row;
    if (n < 256)       { W = Wv; N = 256; row = n;        }
    else if (n < 512)  { W = Wa; N = 256; row = n - 256;  }
    else if (n < 1024) { W = Wf; N = 512; row = n - 512;  }
    else               { W = Wo; N = 256; row = n - 1024; }
    const float w = W[(size_t)k * N + row];
    const __nv_bfloat16 h = __float2bfloat16(w);
    g_wt_hi[(size_t)n * 256 + k] = h;
    g_wt_lo[(size_t)n * 256 + k] = __float2bfloat16(w - __bfloat162float(h));
}

// ---------------- HMMA bf16x3 GEMM core ------------------------------------
// tile 64x128, kb=16, 4-stage cp.async pipeline (prefetch distance 3),
// ONE barrier per iteration. 128 threads (4 warps 2x2), warp tile 32x64.
// A fp32 (80B rows); B bf16 hi/lo 32B rows, chunk-XOR swizzled.
#define AROW  80
#define S_A   0
#define S_BHI 5120
#define S_BLO 9216
#define STGS  13312
#define SMEM_DYN (4 * STGS)        // 53248 B -> 4 CTAs/SM

__device__ __forceinline__ void gemm_core(
    const float* __restrict__ A,
    const __nv_bfloat16* __restrict__ BtHi,
    const __nv_bfloat16* __restrict__ BtLo,
    const float* __restrict__ bias,
    float* __restrict__ C, int M, int N, int bx, int by, char* sp)
{
    const uint32_t s0 = smem_u32(sp);
    const int tid  = threadIdx.x;
    const int wid  = tid >> 5;
    const int lane = tid & 31;
    const int wm   = wid >> 1;
    const int wn   = wid & 1;
    const int row0 = by * 64;
    const int col0 = bx * 128;

    const int q   = lane >> 2;
    const int t2  = (lane & 3) * 2;
    const int lrB = (lane & 7) + (lane >> 4) * 8;
    const int ckB = (lane >> 3) & 1;           // 16B chunk within 32B row

    float acc[2][8][4];
#pragma unroll
    for (int mt = 0; mt < 2; ++mt)
#pragma unroll
        for (int nt = 0; nt < 8; ++nt)
#pragma unroll
            for (int i = 0; i < 4; ++i) acc[mt][nt][i] = 0.f;

    auto load_kb = [&](int kb, int st) {
        const uint32_t sb = s0 + st * STGS;
        // A: 64 rows x 16 floats, 256 x 16B chunks, 2/thread
#pragma unroll
        for (int it = 0; it < 2; ++it) {
            const int chunk = it * 128 + tid;
            const int row = chunk >> 2, c = chunk & 3;
            const int gr  = row0 + row;
            const int vr  = (gr < M) ? gr : 0;
            cp16(sb + S_A + row * AROW + c * 16,
                 A + (size_t)vr * KDIM + kb * 16 + c * 4);
        }
        // B hi/lo: 128 rows x 32B, 512 chunks, 4/thread, XOR swizzle
#pragma unroll
        for (int it = 0; it < 4; ++it) {
            const int chunk = it * 128 + tid;
            const int half = chunk >> 8;
            const int rc = chunk & 255;
            const int r = rc >> 1, c = rc & 1;
            const int csw = c ^ (((r >> 1) ^ (r >> 2)) & 1);
            const __nv_bfloat16* src = (half ? BtLo : BtHi)
                                     + (size_t)(col0 + r) * KDIM + kb * 16 + c * 8;
            cp16(sb + (half ? S_BLO : S_BHI) + r * 32 + csw * 16, src);
        }
    };

    load_kb(0, 0); CP_COMMIT();
    load_kb(1, 1); CP_COMMIT();
    load_kb(2, 2); CP_COMMIT();

    for (int kb = 0; kb < 16; ++kb) {
        CP_WAIT(2);
        __syncthreads();
        if (kb < 13) load_kb(kb + 3, (kb + 3) & 3);
        CP_COMMIT();

        const int s = kb & 3;
        const char*    spA = sp + s * STGS + S_A;
        const uint32_t sbB = s0 + s * STGS;

        // ---- A fragments: fp32 LDS.64 + on-the-fly hi/lo split ----
        uint32_t ahi[2][4], alo[2][4];
#pragma unroll
        for (int mt = 0; mt < 2; ++mt) {
            const int rb = wm * 32 + mt * 16 + q;
#pragma unroll
            for (int i = 0; i < 4; ++i) {
                const int r = rb + (i & 1) * 8;
                const int k = t2 + (i >> 1) * 8;
                const float2 f = *(const float2*)(spA + r * AROW + k * 4);
                __nv_bfloat162 h2 = __floats2bfloat162_rn(f.x, f.y);
                const uint32_t h = *reinterpret_cast<uint32_t*>(&h2);
                const float g0 = __uint_as_float(h << 16);
                const float g1 = __uint_as_float(h & 0xFFFF0000u);
                __nv_bfloat162 l2 = __floats2bfloat162_rn(f.x - g0, f.y - g1);
                ahi[mt][i] = h;
                alo[mt][i] = *reinterpret_cast<uint32_t*>(&l2);
            }
        }
#pragma unroll
        for (int np = 0; np < 4; ++np) {
            const int n = wn * 64 + np * 16 + lrB;
            const uint32_t boff = (uint32_t)(n * 32
                + ((ckB ^ (((n >> 1) ^ (n >> 2)) & 1)) << 4));
            uint32_t bh[4], bl[4];
            ldsm_x4(bh, sbB + S_BHI + boff);
            ldsm_x4(bl, sbB + S_BLO + boff);
#pragma unroll
            for (int mt = 0; mt < 2; ++mt) {
#pragma unroll
                for (int h2 = 0; h2 < 2; ++h2) {
                    float* c = acc[mt][np * 2 + h2];
                    mma_bf16(c, ahi[mt], bh + h2 * 2);
                    mma_bf16(c, ahi[mt], bl + h2 * 2);
                    mma_bf16(c, alo[mt], bh + h2 * 2);
                }
            }
        }
    }

    const int n2 = (lane & 3) * 2;
#pragma unroll
    for (int mt = 0; mt < 2; ++mt) {
        const int mbase = row0 + wm * 32 + mt * 16 + q;
#pragma unroll
        for (int nt = 0; nt < 8; ++nt) {
            const int gc = col0 + wn * 64 + nt * 8 + n2;
            const float bx2 = bias[gc], by2 = bias[gc + 1];
            const float* c = acc[mt][nt];
            if (mbase < M)
                *(float2*)(C + (size_t)mbase * N + gc) =
                    make_float2(c[0] + bx2, c[1] + by2);
            if (mbase + 8 < M)
                *(float2*)(C + (size_t)(mbase + 8) * N + gc) =
                    make_float2(c[2] + bx2, c[3] + by2);
        }
    }
}

// fused val + qo GEMMs in one launch (linearized grid)
#define NVB (2 * 1834)            // val blocks: x=2, y=1834
__global__ __launch_bounds__(128, 4)
void gemm_vq_kernel(const float* __restrict__ Aval,
                    const float* __restrict__ Aqry,
                    const __nv_bfloat16* __restrict__ wth,
                    const __nv_bfloat16* __restrict__ wtl,
                    const float* __restrict__ bval,
                    const float* __restrict__ bqo,
                    float* __restrict__ Cval, float* __restrict__ Cqo)
{
    extern __shared__ __align__(16) char sp[];
    const int bid = blockIdx.x;
    if (bid < NVB) {
        gemm_core(Aval, wth + (size_t)WT_VAL * 256, wtl + (size_t)WT_VAL * 256,
                  bval, Cval, MV, 256, bid & 1, bid >> 1, sp);
    } else {
        const int r = bid - NVB;
        gemm_core(Aqry, wth + (size_t)WT_QRY * 256, wtl + (size_t)WT_QRY * 256,
                  bqo, Cqo, MQ, 768, r % 6, r / 6, sp);
    }
}

__global__ __launch_bounds__(128, 4)
void gemm_out_kernel(const float* __restrict__ A,
                     const __nv_bfloat16* __restrict__ wth,
                     const __nv_bfloat16* __restrict__ wtl,
                     const float* __restrict__ bias,
                     float* __restrict__ C)
{
    extern __shared__ __align__(16) char sp[];
    gemm_core(A, wth + (size_t)WT_OUT * 256, wtl + (size_t)WT_OUT * 256,
              bias, C, MQ, 256, blockIdx.x, blockIdx.y, sp);
}

// ---------------- deformable sampling core --------------------------------
__global__ __launch_bounds__(256)
void msda_sample_kernel(const float* __restrict__ refp)
{
    __shared__ float2 st[NH][4][36];     // [head][corner][point(+pad)]

    const int bq   = blockIdx.x;
    const int lane = threadIdx.x;
    const int h    = threadIdx.y;
    const int b    = bq >> 12;

    const float aval = g_qo[(size_t)bq * 768 + h * 32 + lane];
    float mx = aval;
#pragma unroll
    for (int s = 16; s; s >>= 1) mx = fmaxf(mx, __shfl_xor_sync(0xffffffffu, mx, s));
    const float e = __expf(aval - mx);
    float sm = e;
#pragma unroll
    for (int s = 16; s; s >>= 1) sm += __shfl_xor_sync(0xffffffffu, sm, s);
    const float aw = e / sm;

    {
        const int j  = lane;
        const int lv = j >> 3;
        const int Wl = cWL[lv], Hl = cHL[lv];

        const float2 o2 = *(const float2*)(g_qo + (size_t)bq * 768 + 256
                                           + h * 64 + j * 2);
        const float rx = refp[(size_t)bq * 8 + lv * 2];
        const float ry = refp[(size_t)bq * 8 + lv * 2 + 1];

        const float locx = rx + o2.x * cIW[lv];
        const float locy = ry + o2.y * cIH[lv];
        const float gx = 2.f * locx - 1.f;
        const float gy = 2.f * locy - 1.f;
        const float x = (gx + 1.f) * ((float)Wl * 0.5f) - 0.5f;
        const float y = (gy + 1.f) * ((float)Hl * 0.5f) - 0.5f;

        const float xf = floorf(x), yf = floorf(y);
        const float wx = x - xf,    wy = y - yf;
        const int x0 = (int)xf, y0 = (int)yf;
        const int x1 = x0 + 1,  y1 = y0 + 1;

        const bool vx0 = (x0 >= 0) && (x0 < Wl);
        const bool vx1 = (x1 >= 0) && (x1 < Wl);
        const bool vy0 = (y0 >= 0) && (y0 < Hl);
        const bool vy1 = (y1 >= 0) && (y1 < Hl);

        const int xA = min(max(x0, 0), Wl - 1);
        const int xB = min(max(x1, 0), Wl - 1);
        const int yA = min(max(y0, 0), Hl - 1);
        const int yB = min(max(y1, 0), Hl - 1);

        const int base = cST[lv];
        const int off00 = (base + yA * Wl + xA) << 10;
        const int off10 = (base + yA * Wl + xB) << 10;
        const int off01 = (base + yB * Wl + xA) << 10;
        const int off11 = (base + yB * Wl + xB) << 10;

        const float w00 = (vx0 && vy0) ? aw * (1.f - wx) * (1.f - wy) : 0.f;
        const float w10 = (vx1 && vy0) ? aw * wx         * (1.f - wy) : 0.f;
        const float w01 = (vx0 && vy1) ? aw * (1.f - wx) * wy         : 0.f;
        const float w11 = (vx1 && vy1) ? aw * wx         * wy         : 0.f;

        st[h][0][j] = make_float2(__int_as_float(off00), w00);
        st[h][1][j] = make_float2(__int_as_float(off10), w10);
        st[h][2][j] = make_float2(__int_as_float(off01), w01);
        st[h][3][j] = make_float2(__int_as_float(off11), w11);
    }
    __syncwarp();

    const int g  = lane >> 3;
    const int cq = lane & 7;
    const char* vb = (const char*)(g_v + (size_t)b * LTOT * EMB + h * 32 + cq * 4);
    const float2* owrow = st[h][g];

    float4 acc = make_float4(0.f, 0.f, 0.f, 0.f);
#pragma unroll 4
    for (int p = 0; p < 32; p += 2) {
        const float4 ow2 = *(const float4*)(owrow + p);
        const float4 va  = *(const float4*)(vb + __float_as_int(ow2.x));
        const float4 vbv = *(const float4*)(vb + __float_as_int(ow2.z));
        acc.x = fmaf(ow2.y, va.x, acc.x);
        acc.y = fmaf(ow2.y, va.y, acc.y);
        acc.z = fmaf(ow2.y, va.z, acc.z);
        acc.w = fmaf(ow2.y, va.w, acc.w);
        acc.x = fmaf(ow2.w, vbv.x, acc.x);
        acc.y = fmaf(ow2.w, vbv.y, acc.y);
        acc.z = fmaf(ow2.w, vbv.z, acc.z);
        acc.w = fmaf(ow2.w, vbv.w, acc.w);
    }
#pragma unroll
    for (int s = 8; s <= 16; s <<= 1) {
        acc.x += __shfl_xor_sync(0xffffffffu, acc.x, s);
        acc.y += __shfl_xor_sync(0xffffffffu, acc.y, s);
        acc.z += __shfl_xor_sync(0xffffffffu, acc.z, s);
        acc.w += __shfl_xor_sync(0xffffffffu, acc.w, s);
    }
    if (g == 0)
        *(float4*)(g_tmp + (size_t)bq * EMB + h * 32 + cq * 4) = acc;
}

// ---------------- launch ---------------------------------------------------
extern "C" void kernel_launch(void* const* d_in, const int* in_sizes, int n_in,
                              void* d_out, int out_size)
{
    const float* query  = (const float*)d_in[0];
    const float* value  = (const float*)d_in[1];
    const float* refp   = (const float*)d_in[2];
    const float* W_off  = (const float*)d_in[4];
    const float* b_off  = (const float*)d_in[5];
    const float* W_attn = (const float*)d_in[6];
    const float* b_attn = (const float*)d_in[7];
    const float* W_val  = (const float*)d_in[8];
    const float* b_val  = (const float*)d_in[9];
    const float* W_out  = (const float*)d_in[10];
    const float* b_out  = (const float*)d_in[11];
    float* out = (float*)d_out;

    float *gv, *gqo, *gtmp, *gbqo;
    __nv_bfloat16 *wth, *wtl;
    cudaGetSymbolAddress((void**)&gv,   g_v);
    cudaGetSymbolAddress((void**)&gqo,  g_qo);
    cudaGetSymbolAddress((void**)&gtmp, g_tmp);
    cudaGetSymbolAddress((void**)&gbqo, g_bqo);
    cudaGetSymbolAddress((void**)&wth,  g_wt_hi);
    cudaGetSymbolAddress((void**)&wtl,  g_wt_lo);

    cudaFuncSetAttribute(gemm_vq_kernel,
                         cudaFuncAttributeMaxDynamicSharedMemorySize, SMEM_DYN);
    cudaFuncSetAttribute(gemm_out_kernel,
                         cudaFuncAttributeMaxDynamicSharedMemorySize, SMEM_DYN);

    // 0) weight transpose + bf16 hi/lo split + fused bias
    prep_weights<<<1280, 256>>>(W_val, W_attn, W_off, W_out, b_attn, b_off);

    // 1) fused: value projection -> g_v  AND  attn+off -> g_qo
    gemm_vq_kernel<<<NVB + 6 * (MQ / 64), 128, SMEM_DYN>>>(
        value, query, wth, wtl, b_val, gbqo, gv, gqo);

    // 2) softmax + bilinear sampling -> g_tmp
    msda_sample_kernel<<<MQ, dim3(32, 8)>>>(refp);

    // 3) output projection -> d_out
    gemm_out_kernel<<<dim3(2, MQ / 64), 128, SMEM_DYN>>>(
        gtmp, wth, wtl, b_out, out);
}

// round 13
// speedup vs baseline: 1.1332x; 1.1332x over previous
#include <cuda_runtime.h>
#include <cuda_bf16.h>
#include <cuda_fp16.h>
#include <cstdint>

// ---------------- problem constants ----------------
#define BS   6
#define NQ   4096
#define EMB  256
#define NH   8
#define LTOT 19560            // 92*160 + 46*80 + 23*40 + 12*20
#define MQ   (BS * NQ)        // 24576
#define MV   (BS * LTOT)      // 117360
#define KDIM 256

// ---------------- scratch (device globals; no cudaMalloc allowed) ----------
__device__ __half g_v [(size_t)MV * EMB];    // fp16 value cache (sampler-only)
__device__ float g_qo [(size_t)MQ * 768];    // [attn 256 | off 512] per row
__device__ float g_tmp[(size_t)MQ * EMB];
__device__ float g_bqo[768];                 // fused bias [b_attn | b_off]

// transposed + hi/lo split weights, rows = output col n, 256 k each
// layout: [val 256 | attn 256 | off 512 | out 256] = 1280 rows
#define WT_VAL  0
#define WT_QRY  256
#define WT_OUT  1024
__device__ __align__(128) __nv_bfloat16 g_wt_hi[1280 * 256];
__device__ __align__(128) __nv_bfloat16 g_wt_lo[1280 * 256];

__constant__ int   cHL[4] = {92, 46, 23, 12};
__constant__ int   cWL[4] = {160, 80, 40, 20};
__constant__ int   cST[4] = {0, 14720, 18400, 19320};
__constant__ float cIW[4] = {1.f/160.f, 1.f/80.f, 1.f/40.f, 1.f/20.f};
__constant__ float cIH[4] = {1.f/92.f,  1.f/46.f, 1.f/23.f, 1.f/12.f};

// ---------------- helpers ---------------------------------------------------
__device__ __forceinline__ uint32_t smem_u32(const void* p) {
    uint32_t a;
    asm("{ .reg .u64 t; cvta.to.shared.u64 t, %1; cvt.u32.u64 %0, t; }"
        : "=r"(a) : "l"(p));
    return a;
}
__device__ __forceinline__ void ldsm_x4(uint32_t* r, uint32_t addr) {
    asm volatile("ldmatrix.sync.aligned.m8n8.x4.shared.b16 {%0,%1,%2,%3}, [%4];"
                 : "=r"(r[0]), "=r"(r[1]), "=r"(r[2]), "=r"(r[3]) : "r"(addr));
}
__device__ __forceinline__ void mma_bf16(float* c, const uint32_t* a,
                                         const uint32_t* b) {
    asm volatile(
        "mma.sync.aligned.m16n8k16.row.col.f32.bf16.bf16.f32 "
        "{%0,%1,%2,%3}, {%4,%5,%6,%7}, {%8,%9}, {%0,%1,%2,%3};"
        : "+f"(c[0]), "+f"(c[1]), "+f"(c[2]), "+f"(c[3])
        : "r"(a[0]), "r"(a[1]), "r"(a[2]), "r"(a[3]), "r"(b[0]), "r"(b[1]));
}
__device__ __forceinline__ void cp16(uint32_t dst, const void* src) {
    asm volatile("cp.async.cg.shared.global [%0], [%1], 16;"
                 :: "r"(dst), "l"(src) : "memory");
}
#define CP_COMMIT() asm volatile("cp.async.commit_group;" ::: "memory")
#define CP_WAIT(n)  asm volatile("cp.async.wait_group " #n ";" ::: "memory")

// ---------------- weight prep: transpose + bf16 hi/lo split ---------------
__global__ void prep_weights(const float* __restrict__ Wv,
                             const float* __restrict__ Wa,
                             const float* __restrict__ Wf,
                             const float* __restrict__ Wo,
                             const float* __restrict__ ba,
                             const float* __restrict__ bf)
{
    const int n = blockIdx.x;
    const int k = threadIdx.x;
    if (n == 0) g_bqo[k]       = ba[k];
    if (n == 1) g_bqo[256 + k] = bf[k];
    if (n == 2) g_bqo[512 + k] = bf[256 + k];
    const float* W; int N, row;
    if (n < 256)       { W = Wv; N = 256; row = n;        }
    else if (n < 512)  { W = Wa; N = 256; row = n - 256;  }
    else if (n < 1024) { W = Wf; N = 512; row = n - 512;  }
    else               { W = Wo; N = 256; row = n - 1024; }
    const float w = W[(size_t)k * N + row];
    const __nv_bfloat16 h = __float2bfloat16(w);
    g_wt_hi[(size_t)n * 256 + k] = h;
    g_wt_lo[(size_t)n * 256 + k] = __float2bfloat16(w - __bfloat162float(h));
}

// ---------------- HMMA bf16x3 GEMM core (R10 geometry) ---------------------
// tile 64x128, kb=32, 2-stage cp.async, 128 threads (4 warps 2x2).
// A fp32 in smem (160B rows) + per-fragment hi/lo split;
// B bf16 hi/lo, 64B rows with XOR-16B-chunk swizzle.
#define AROW  160
#define S_A   0
#define S_BHI 10240
#define S_BLO 18432
#define STGB  26624
#define SMEM_DYN (2 * STGB)        // 53248 B -> 4 CTAs/SM

template <typename OutT>
__device__ __forceinline__ void gemm_core(
    const float* __restrict__ A,
    const __nv_bfloat16* __restrict__ BtHi,
    const __nv_bfloat16* __restrict__ BtLo,
    const float* __restrict__ bias,
    OutT* __restrict__ C, int M, int N, int bx, int by, char* sp)
{
    const uint32_t s0 = smem_u32(sp);
    const int tid  = threadIdx.x;
    const int wid  = tid >> 5;
    const int lane = tid & 31;
    const int wm   = wid >> 1;
    const int wn   = wid & 1;
    const int row0 = by * 64;
    const int col0 = bx * 128;

    const int q   = lane >> 2;
    const int t2  = (lane & 3) * 2;
    const int lrB = (lane & 7) + (lane >> 4) * 8;
    const int lkB = ((lane >> 3) & 1) * 8;

    float acc[2][8][4];
#pragma unroll
    for (int mt = 0; mt < 2; ++mt)
#pragma unroll
        for (int nt = 0; nt < 8; ++nt)
#pragma unroll
            for (int i = 0; i < 4; ++i) acc[mt][nt][i] = 0.f;

    auto load_kb = [&](int kb, int st) {
        const uint32_t sb = s0 + st * STGB;
#pragma unroll
        for (int it = 0; it < 4; ++it) {
            const int chunk = it * 128 + tid;
            const int row = chunk >> 3, c = chunk & 7;
            const int gr  = row0 + row;
            const int vr  = (gr < M) ? gr : 0;
            cp16(sb + S_A + row * AROW + c * 16,
                 A + (size_t)vr * KDIM + kb * 32 + c * 4);
        }
#pragma unroll
        for (int it = 0; it < 8; ++it) {
            const int chunk = it * 128 + tid;
            const int half = chunk >> 9;
            const int rc = chunk & 511;
            const int r = rc >> 2, c = rc & 3;
            const int csw = c ^ ((r >> 1) & 3);
            const __nv_bfloat16* src = (half ? BtLo : BtHi)
                                     + (size_t)(col0 + r) * KDIM + kb * 32 + c * 8;
            cp16(sb + (half ? S_BLO : S_BHI) + r * 64 + csw * 16, src);
        }
    };

    load_kb(0, 0);
    CP_COMMIT();

    int s = 0;
    for (int kb = 0; kb < 8; ++kb) {
        if (kb < 7) {
            load_kb(kb + 1, s ^ 1);
            CP_COMMIT();
            CP_WAIT(1);
        } else {
            CP_WAIT(0);
        }
        __syncthreads();

        const char*    spA = sp + s * STGB + S_A;
        const uint32_t sbB = s0 + s * STGB;

#pragma unroll
        for (int ks = 0; ks < 2; ++ks) {
            const int k0 = ks * 16;
            uint32_t ahi[2][4], alo[2][4];
#pragma unroll
            for (int mt = 0; mt < 2; ++mt) {
                const int rb = wm * 32 + mt * 16 + q;
#pragma unroll
                for (int i = 0; i < 4; ++i) {
                    const int r = rb + (i & 1) * 8;
                    const int k = k0 + t2 + (i >> 1) * 8;
                    const float2 f = *(const float2*)(spA + r * AROW + k * 4);
                    __nv_bfloat162 h2 = __floats2bfloat162_rn(f.x, f.y);
                    const uint32_t h = *reinterpret_cast<uint32_t*>(&h2);
                    const float g0 = __uint_as_float(h << 16);
                    const float g1 = __uint_as_float(h & 0xFFFF0000u);
                    __nv_bfloat162 l2 = __floats2bfloat162_rn(f.x - g0, f.y - g1);
                    ahi[mt][i] = h;
                    alo[mt][i] = *reinterpret_cast<uint32_t*>(&l2);
                }
            }
            const int ck = (k0 + lkB) >> 3;
#pragma unroll
            for (int np = 0; np < 4; ++np) {
                const int n = wn * 64 + np * 16 + lrB;
                const uint32_t boff = (uint32_t)(n * 64
                                      + ((ck ^ ((n >> 1) & 3)) << 4));
                uint32_t bh[4], bl[4];
                ldsm_x4(bh, sbB + S_BHI + boff);
                ldsm_x4(bl, sbB + S_BLO + boff);
#pragma unroll
                for (int mt = 0; mt < 2; ++mt) {
#pragma unroll
                    for (int h2 = 0; h2 < 2; ++h2) {
                        float* c = acc[mt][np * 2 + h2];
                        mma_bf16(c, ahi[mt], bh + h2 * 2);
                        mma_bf16(c, ahi[mt], bl + h2 * 2);
                        mma_bf16(c, alo[mt], bh + h2 * 2);
                    }
                }
            }
        }
        __syncthreads();
        s ^= 1;
    }

    const int n2 = (lane & 3) * 2;
#pragma unroll
    for (int mt = 0; mt < 2; ++mt) {
        const int mbase = row0 + wm * 32 + mt * 16 + q;
#pragma unroll
        for (int nt = 0; nt < 8; ++nt) {
            const int gc = col0 + wn * 64 + nt * 8 + n2;
            const float bx2 = bias[gc], by2 = bias[gc + 1];
            const float* c = acc[mt][nt];
#pragma unroll
            for (int half = 0; half < 2; ++half) {
                const int m = mbase + half * 8;
                if (m < M) {
                    if constexpr (sizeof(OutT) == 2) {
                        *(__half2*)((__half*)C + (size_t)m * N + gc) =
                            __floats2half2_rn(c[half * 2 + 0] + bx2,
                                              c[half * 2 + 1] + by2);
                    } else {
                        *(float2*)((float*)C + (size_t)m * N + gc) =
                            make_float2(c[half * 2 + 0] + bx2,
                                        c[half * 2 + 1] + by2);
                    }
                }
            }
        }
    }
}

// fused val + qo GEMMs in one launch (linearized grid)
#define NVB (2 * 1834)            // val blocks: x=2, y=1834
__global__ __launch_bounds__(128, 4)
void gemm_vq_kernel(const float* __restrict__ Aval,
                    const float* __restrict__ Aqry,
                    const __nv_bfloat16* __restrict__ wth,
                    const __nv_bfloat16* __restrict__ wtl,
                    const float* __restrict__ bval,
                    const float* __restrict__ bqo,
                    __half* __restrict__ Cval, float* __restrict__ Cqo)
{
    extern __shared__ __align__(16) char sp[];
    const int bid = blockIdx.x;
    if (bid < NVB) {
        gemm_core<__half>(Aval, wth + (size_t)WT_VAL * 256,
                          wtl + (size_t)WT_VAL * 256,
                          bval, Cval, MV, 256, bid & 1, bid >> 1, sp);
    } else {
        const int r = bid - NVB;
        gemm_core<float>(Aqry, wth + (size_t)WT_QRY * 256,
                         wtl + (size_t)WT_QRY * 256,
                         bqo, Cqo, MQ, 768, r % 6, r / 6, sp);
    }
}

__global__ __launch_bounds__(128, 4)
void gemm_out_kernel(const float* __restrict__ A,
                     const __nv_bfloat16* __restrict__ wth,
                     const __nv_bfloat16* __restrict__ wtl,
                     const float* __restrict__ bias,
                     float* __restrict__ C)
{
    extern __shared__ __align__(16) char sp[];
    gemm_core<float>(A, wth + (size_t)WT_OUT * 256, wtl + (size_t)WT_OUT * 256,
                     bias, C, MQ, 256, blockIdx.x, blockIdx.y, sp);
}

// ---------------- deformable sampling core --------------------------------
// Phase 1: lane = point; 4 (byte-offset, weight) pairs -> st[h][corner][pt].
// Phase 2: lane = (corner, channel-quad); per 2 points: 1 LDS.128 + 2 LDG.64
// of fp16 values (512B per spatial location), cvt to fp32, FMA.
__global__ __launch_bounds__(256)
void msda_sample_kernel(const float* __restrict__ refp)
{
    __shared__ float2 st[NH][4][36];     // [head][corner][point(+pad)]

    const int bq   = blockIdx.x;
    const int lane = threadIdx.x;
    const int h    = threadIdx.y;
    const int b    = bq >> 12;

    const float aval = g_qo[(size_t)bq * 768 + h * 32 + lane];
    float mx = aval;
#pragma unroll
    for (int s = 16; s; s >>= 1) mx = fmaxf(mx, __shfl_xor_sync(0xffffffffu, mx, s));
    const float e = __expf(aval - mx);
    float sm = e;
#pragma unroll
    for (int s = 16; s; s >>= 1) sm += __shfl_xor_sync(0xffffffffu, sm, s);
    const float aw = e / sm;

    {
        const int j  = lane;
        const int lv = j >> 3;
        const int Wl = cWL[lv], Hl = cHL[lv];

        const float2 o2 = *(const float2*)(g_qo + (size_t)bq * 768 + 256
                                           + h * 64 + j * 2);
        const float rx = refp[(size_t)bq * 8 + lv * 2];
        const float ry = refp[(size_t)bq * 8 + lv * 2 + 1];

        const float locx = rx + o2.x * cIW[lv];
        const float locy = ry + o2.y * cIH[lv];
        const float gx = 2.f * locx - 1.f;
        const float gy = 2.f * locy - 1.f;
        const float x = (gx + 1.f) * ((float)Wl * 0.5f) - 0.5f;
        const float y = (gy + 1.f) * ((float)Hl * 0.5f) - 0.5f;

        const float xf = floorf(x), yf = floorf(y);
        const float wx = x - xf,    wy = y - yf;
        const int x0 = (int)xf, y0 = (int)yf;
        const int x1 = x0 + 1,  y1 = y0 + 1;

        const bool vx0 = (x0 >= 0) && (x0 < Wl);
        const bool vx1 = (x1 >= 0) && (x1 < Wl);
        const bool vy0 = (y0 >= 0) && (y0 < Hl);
        const bool vy1 = (y1 >= 0) && (y1 < Hl);

        const int xA = min(max(x0, 0), Wl - 1);
        const int xB = min(max(x1, 0), Wl - 1);
        const int yA = min(max(y0, 0), Hl - 1);
        const int yB = min(max(y1, 0), Hl - 1);

        // byte offsets: 512 B per spatial location (fp16)
        const int base = cST[lv];
        const int off00 = (base + yA * Wl + xA) << 9;
        const int off10 = (base + yA * Wl + xB) << 9;
        const int off01 = (base + yB * Wl + xA) << 9;
        const int off11 = (base + yB * Wl + xB) << 9;

        const float w00 = (vx0 && vy0) ? aw * (1.f - wx) * (1.f - wy) : 0.f;
        const float w10 = (vx1 && vy0) ? aw * wx         * (1.f - wy) : 0.f;
        const float w01 = (vx0 && vy1) ? aw * (1.f - wx) * wy         : 0.f;
        const float w11 = (vx1 && vy1) ? aw * wx         * wy         : 0.f;

        st[h][0][j] = make_float2(__int_as_float(off00), w00);
        st[h][1][j] = make_float2(__int_as_float(off10), w10);
        st[h][2][j] = make_float2(__int_as_float(off01), w01);
        st[h][3][j] = make_float2(__int_as_float(off11), w11);
    }
    __syncwarp();

    const int g  = lane >> 3;
    const int cq = lane & 7;
    const char* vb = (const char*)(g_v + (size_t)b * LTOT * EMB + h * 32 + cq * 4);
    const float2* owrow = st[h][g];

    float4 acc = make_float4(0.f, 0.f, 0.f, 0.f);
#pragma unroll 4
    for (int p = 0; p < 32; p += 2) {
        const float4 ow2 = *(const float4*)(owrow + p);
        const uint2 ua = *(const uint2*)(vb + __float_as_int(ow2.x));
        const uint2 ub = *(const uint2*)(vb + __float_as_int(ow2.z));
        const float2 a01 = __half22float2(*(const __half2*)&ua.x);
        const float2 a23 = __half22float2(*(const __half2*)&ua.y);
        const float2 b01 = __half22float2(*(const __half2*)&ub.x);
        const float2 b23 = __half22float2(*(const __half2*)&ub.y);
        acc.x = fmaf(ow2.y, a01.x, acc.x);
        acc.y = fmaf(ow2.y, a01.y, acc.y);
        acc.z = fmaf(ow2.y, a23.x, acc.z);
        acc.w = fmaf(ow2.y, a23.y, acc.w);
        acc.x = fmaf(ow2.w, b01.x, acc.x);
        acc.y = fmaf(ow2.w, b01.y, acc.y);
        acc.z = fmaf(ow2.w, b23.x, acc.z);
        acc.w = fmaf(ow2.w, b23.y, acc.w);
    }
#pragma unroll
    for (int s = 8; s <= 16; s <<= 1) {
        acc.x += __shfl_xor_sync(0xffffffffu, acc.x, s);
        acc.y += __shfl_xor_sync(0xffffffffu, acc.y, s);
        acc.z += __shfl_xor_sync(0xffffffffu, acc.z, s);
        acc.w += __shfl_xor_sync(0xffffffffu, acc.w, s);
    }
    if (g == 0)
        *(float4*)(g_tmp + (size_t)bq * EMB + h * 32 + cq * 4) = acc;
}

// ---------------- launch ---------------------------------------------------
extern "C" void kernel_launch(void* const* d_in, const int* in_sizes, int n_in,
                              void* d_out, int out_size)
{
    const float* query  = (const float*)d_in[0];
    const float* value  = (const float*)d_in[1];
    const float* refp   = (const float*)d_in[2];
    const float* W_off  = (const float*)d_in[4];
    const float* b_off  = (const float*)d_in[5];
    const float* W_attn = (const float*)d_in[6];
    const float* b_attn = (const float*)d_in[7];
    const float* W_val  = (const float*)d_in[8];
    const float* b_val  = (const float*)d_in[9];
    const float* W_out  = (const float*)d_in[10];
    const float* b_out  = (const float*)d_in[11];
    float* out = (float*)d_out;

    float *gqo, *gtmp, *gbqo;
    __half* gv;
    __nv_bfloat16 *wth, *wtl;
    cudaGetSymbolAddress((void**)&gv,   g_v);
    cudaGetSymbolAddress((void**)&gqo,  g_qo);
    cudaGetSymbolAddress((void**)&gtmp, g_tmp);
    cudaGetSymbolAddress((void**)&gbqo, g_bqo);
    cudaGetSymbolAddress((void**)&wth,  g_wt_hi);
    cudaGetSymbolAddress((void**)&wtl,  g_wt_lo);

    cudaFuncSetAttribute(gemm_vq_kernel,
                         cudaFuncAttributeMaxDynamicSharedMemorySize, SMEM_DYN);
    cudaFuncSetAttribute(gemm_out_kernel,
                         cudaFuncAttributeMaxDynamicSharedMemorySize, SMEM_DYN);

    // 0) weight transpose + bf16 hi/lo split + fused bias
    prep_weights<<<1280, 256>>>(W_val, W_attn, W_off, W_out, b_attn, b_off);

    // 1) fused: value projection (fp16 out) -> g_v  AND  attn+off -> g_qo
    gemm_vq_kernel<<<NVB + 6 * (MQ / 64), 128, SMEM_DYN>>>(
        value, query, wth, wtl, b_val, gbqo, gv, gqo);

    // 2) softmax + bilinear sampling -> g_tmp
    msda_sample_kernel<<<MQ, dim3(32, 8)>>>(refp);

    // 3) output projection -> d_out
    gemm_out_kernel<<<dim3(2, MQ / 64), 128, SMEM_DYN>>>(
        gtmp, wth, wtl, b_out, out);
}

// round 14
// speedup vs baseline: 1.2518x; 1.1047x over previous
#include <cuda_runtime.h>
#include <cuda_bf16.h>
#include <cuda_fp16.h>
#include <cstdint>

// ---------------- problem constants ----------------
#define BS   6
#define NQ   4096
#define EMB  256
#define NH   8
#define LTOT 19560            // 92*160 + 46*80 + 23*40 + 12*20
#define MQ   (BS * NQ)        // 24576
#define MV   (BS * LTOT)      // 117360
#define KDIM 256

// ---------------- scratch (device globals; no cudaMalloc allowed) ----------
// g_v layout: [b][head][location][32 ch] fp16  (64 B per (head,loc))
__device__ __half g_v [(size_t)MV * EMB];
__device__ float g_qo [(size_t)MQ * 768];    // [attn 256 | off 512] per row
__device__ float g_tmp[(size_t)MQ * EMB];
__device__ float g_bqo[768];                 // fused bias [b_attn | b_off]

// transposed + hi/lo split weights, rows = output col n, 256 k each
// layout: [val 256 | attn 256 | off 512 | out 256] = 1280 rows
#define WT_VAL  0
#define WT_QRY  256
#define WT_OUT  1024
__device__ __align__(128) __nv_bfloat16 g_wt_hi[1280 * 256];
__device__ __align__(128) __nv_bfloat16 g_wt_lo[1280 * 256];

__constant__ int   cHL[4] = {92, 46, 23, 12};
__constant__ int   cWL[4] = {160, 80, 40, 20};
__constant__ int   cST[4] = {0, 14720, 18400, 19320};
__constant__ float cIW[4] = {1.f/160.f, 1.f/80.f, 1.f/40.f, 1.f/20.f};
__constant__ float cIH[4] = {1.f/92.f,  1.f/46.f, 1.f/23.f, 1.f/12.f};

// ---------------- helpers ---------------------------------------------------
__device__ __forceinline__ uint32_t smem_u32(const void* p) {
    uint32_t a;
    asm("{ .reg .u64 t; cvta.to.shared.u64 t, %1; cvt.u32.u64 %0, t; }"
        : "=r"(a) : "l"(p));
    return a;
}
__device__ __forceinline__ void ldsm_x4(uint32_t* r, uint32_t addr) {
    asm volatile("ldmatrix.sync.aligned.m8n8.x4.shared.b16 {%0,%1,%2,%3}, [%4];"
                 : "=r"(r[0]), "=r"(r[1]), "=r"(r[2]), "=r"(r[3]) : "r"(addr));
}
__device__ __forceinline__ void mma_bf16(float* c, const uint32_t* a,
                                         const uint32_t* b) {
    asm volatile(
        "mma.sync.aligned.m16n8k16.row.col.f32.bf16.bf16.f32 "
        "{%0,%1,%2,%3}, {%4,%5,%6,%7}, {%8,%9}, {%0,%1,%2,%3};"
        : "+f"(c[0]), "+f"(c[1]), "+f"(c[2]), "+f"(c[3])
        : "r"(a[0]), "r"(a[1]), "r"(a[2]), "r"(a[3]), "r"(b[0]), "r"(b[1]));
}
__device__ __forceinline__ void cp16(uint32_t dst, const void* src) {
    asm volatile("cp.async.cg.shared.global [%0], [%1], 16;"
                 :: "r"(dst), "l"(src) : "memory");
}
#define CP_COMMIT() asm volatile("cp.async.commit_group;" ::: "memory")
#define CP_WAIT(n)  asm volatile("cp.async.wait_group " #n ";" ::: "memory")

// ---------------- weight prep: transpose + bf16 hi/lo split ---------------
__global__ void prep_weights(const float* __restrict__ Wv,
                             const float* __restrict__ Wa,
                             const float* __restrict__ Wf,
                             const float* __restrict__ Wo,
                             const float* __restrict__ ba,
                             const float* __restrict__ bf)
{
    const int n = blockIdx.x;
    const int k = threadIdx.x;
    if (n == 0) g_bqo[k]       = ba[k];
    if (n == 1) g_bqo[256 + k] = bf[k];
    if (n == 2) g_bqo[512 + k] = bf[256 + k];
    const float* W; int N, row;
    if (n < 256)       { W = Wv; N = 256; row = n;        }
    else if (n < 512)  { W = Wa; N = 256; row = n - 256;  }
    else if (n < 1024) { W = Wf; N = 512; row = n - 512;  }
    else               { W = Wo; N = 256; row = n - 1024; }
    const float w = W[(size_t)k * N + row];
    const __nv_bfloat16 h = __float2bfloat16(w);
    g_wt_hi[(size_t)n * 256 + k] = h;
    g_wt_lo[(size_t)n * 256 + k] = __float2bfloat16(w - __bfloat162float(h));
}

// ---------------- HMMA bf16x3 GEMM core (R10 geometry) ---------------------
// tile 64x128, kb=32, 2-stage cp.async, 128 threads (4 warps 2x2).
#define AROW  160
#define S_A   0
#define S_BHI 10240
#define S_BLO 18432
#define STGB  26624
#define SMEM_DYN (2 * STGB)        // 53248 B -> 4 CTAs/SM

template <typename OutT, bool HSPLIT>
__device__ __forceinline__ void gemm_core(
    const float* __restrict__ A,
    const __nv_bfloat16* __restrict__ BtHi,
    const __nv_bfloat16* __restrict__ BtLo,
    const float* __restrict__ bias,
    OutT* __restrict__ C, int M, int N, int bx, int by, char* sp)
{
    const uint32_t s0 = smem_u32(sp);
    const int tid  = threadIdx.x;
    const int wid  = tid >> 5;
    const int lane = tid & 31;
    const int wm   = wid >> 1;
    const int wn   = wid & 1;
    const int row0 = by * 64;
    const int col0 = bx * 128;

    const int q   = lane >> 2;
    const int t2  = (lane & 3) * 2;
    const int lrB = (lane & 7) + (lane >> 4) * 8;
    const int lkB = ((lane >> 3) & 1) * 8;

    float acc[2][8][4];
#pragma unroll
    for (int mt = 0; mt < 2; ++mt)
#pragma unroll
        for (int nt = 0; nt < 8; ++nt)
#pragma unroll
            for (int i = 0; i < 4; ++i) acc[mt][nt][i] = 0.f;

    auto load_kb = [&](int kb, int st) {
        const uint32_t sb = s0 + st * STGB;
#pragma unroll
        for (int it = 0; it < 4; ++it) {
            const int chunk = it * 128 + tid;
            const int row = chunk >> 3, c = chunk & 7;
            const int gr  = row0 + row;
            const int vr  = (gr < M) ? gr : 0;
            cp16(sb + S_A + row * AROW + c * 16,
                 A + (size_t)vr * KDIM + kb * 32 + c * 4);
        }
#pragma unroll
        for (int it = 0; it < 8; ++it) {
            const int chunk = it * 128 + tid;
            const int half = chunk >> 9;
            const int rc = chunk & 511;
            const int r = rc >> 2, c = rc & 3;
            const int csw = c ^ ((r >> 1) & 3);
            const __nv_bfloat16* src = (half ? BtLo : BtHi)
                                     + (size_t)(col0 + r) * KDIM + kb * 32 + c * 8;
            cp16(sb + (half ? S_BLO : S_BHI) + r * 64 + csw * 16, src);
        }
    };

    load_kb(0, 0);
    CP_COMMIT();

    int s = 0;
    for (int kb = 0; kb < 8; ++kb) {
        if (kb < 7) {
            load_kb(kb + 1, s ^ 1);
            CP_COMMIT();
            CP_WAIT(1);
        } else {
            CP_WAIT(0);
        }
        __syncthreads();

        const char*    spA = sp + s * STGB + S_A;
        const uint32_t sbB = s0 + s * STGB;

#pragma unroll
        for (int ks = 0; ks < 2; ++ks) {
            const int k0 = ks * 16;
            uint32_t ahi[2][4], alo[2][4];
#pragma unroll
            for (int mt = 0; mt < 2; ++mt) {
                const int rb = wm * 32 + mt * 16 + q;
#pragma unroll
                for (int i = 0; i < 4; ++i) {
                    const int r = rb + (i & 1) * 8;
                    const int k = k0 + t2 + (i >> 1) * 8;
                    const float2 f = *(const float2*)(spA + r * AROW + k * 4);
                    __nv_bfloat162 h2 = __floats2bfloat162_rn(f.x, f.y);
                    const uint32_t h = *reinterpret_cast<uint32_t*>(&h2);
                    const float g0 = __uint_as_float(h << 16);
                    const float g1 = __uint_as_float(h & 0xFFFF0000u);
                    __nv_bfloat162 l2 = __floats2bfloat162_rn(f.x - g0, f.y - g1);
                    ahi[mt][i] = h;
                    alo[mt][i] = *reinterpret_cast<uint32_t*>(&l2);
                }
            }
            const int ck = (k0 + lkB) >> 3;
#pragma unroll
            for (int np = 0; np < 4; ++np) {
                const int n = wn * 64 + np * 16 + lrB;
                const uint32_t boff = (uint32_t)(n * 64
                                      + ((ck ^ ((n >> 1) & 3)) << 4));
                uint32_t bh[4], bl[4];
                ldsm_x4(bh, sbB + S_BHI + boff);
                ldsm_x4(bl, sbB + S_BLO + boff);
#pragma unroll
                for (int mt = 0; mt < 2; ++mt) {
#pragma unroll
                    for (int h2 = 0; h2 < 2; ++h2) {
                        float* c = acc[mt][np * 2 + h2];
                        mma_bf16(c, ahi[mt], bh + h2 * 2);
                        mma_bf16(c, ahi[mt], bl + h2 * 2);
                        mma_bf16(c, alo[mt], bh + h2 * 2);
                    }
                }
            }
        }
        __syncthreads();
        s ^= 1;
    }

    const int n2 = (lane & 3) * 2;
#pragma unroll
    for (int mt = 0; mt < 2; ++mt) {
        const int mbase = row0 + wm * 32 + mt * 16 + q;
#pragma unroll
        for (int nt = 0; nt < 8; ++nt) {
            const int gc = col0 + wn * 64 + nt * 8 + n2;
            const float bx2 = bias[gc], by2 = bias[gc + 1];
            const float* c = acc[mt][nt];
#pragma unroll
            for (int half = 0; half < 2; ++half) {
                const int m = mbase + half * 8;
                if (m < M) {
                    if constexpr (HSPLIT) {
                        // head-split fp16: [b][head][loc][32ch]
                        const int b   = m / LTOT;
                        const int loc = m - b * LTOT;
                        const int hh  = gc >> 5;
                        const int ch  = gc & 31;
                        const size_t addr =
                            (((size_t)(b * NH + hh) * LTOT + loc) << 5) + ch;
                        *(__half2*)((__half*)C + addr) =
                            __floats2half2_rn(c[half * 2 + 0] + bx2,
                                              c[half * 2 + 1] + by2);
                    } else {
                        *(float2*)((float*)C + (size_t)m * N + gc) =
                            make_float2(c[half * 2 + 0] + bx2,
                                        c[half * 2 + 1] + by2);
                    }
                }
            }
        }
    }
}

// fused val + qo GEMMs in one launch (linearized grid)
#define NVB (2 * 1834)            // val blocks: x=2, y=1834
__global__ __launch_bounds__(128, 4)
void gemm_vq_kernel(const float* __restrict__ Aval,
                    const float* __restrict__ Aqry,
                    const __nv_bfloat16* __restrict__ wth,
                    const __nv_bfloat16* __restrict__ wtl,
                    const float* __restrict__ bval,
                    const float* __restrict__ bqo,
                    __half* __restrict__ Cval, float* __restrict__ Cqo)
{
    extern __shared__ __align__(16) char sp[];
    const int bid = blockIdx.x;
    if (bid < NVB) {
        gemm_core<__half, true>(Aval, wth + (size_t)WT_VAL * 256,
                                wtl + (size_t)WT_VAL * 256,
                                bval, Cval, MV, 256, bid & 1, bid >> 1, sp);
    } else {
        const int r = bid - NVB;
        gemm_core<float, false>(Aqry, wth + (size_t)WT_QRY * 256,
                                wtl + (size_t)WT_QRY * 256,
                                bqo, Cqo, MQ, 768, r % 6, r / 6, sp);
    }
}

__global__ __launch_bounds__(128, 4)
void gemm_out_kernel(const float* __restrict__ A,
                     const __nv_bfloat16* __restrict__ wth,
                     const __nv_bfloat16* __restrict__ wtl,
                     const float* __restrict__ bias,
                     float* __restrict__ C)
{
    extern __shared__ __align__(16) char sp[];
    gemm_core<float, false>(A, wth + (size_t)WT_OUT * 256,
                            wtl + (size_t)WT_OUT * 256,
                            bias, C, MQ, 256, blockIdx.x, blockIdx.y, sp);
}

// ---------------- deformable sampling core --------------------------------
// g_v is head-split: [b][head][loc][32ch fp16] -> 64 B per (head,loc);
// adjacent-x corners share a 128 B line when x0 is even.
__global__ __launch_bounds__(256)
void msda_sample_kernel(const float* __restrict__ refp)
{
    __shared__ float2 st[NH][4][36];     // [head][corner][point(+pad)]

    const int bq   = blockIdx.x;
    const int lane = threadIdx.x;
    const int h    = threadIdx.y;
    const int b    = bq >> 12;

    const float aval = g_qo[(size_t)bq * 768 + h * 32 + lane];
    float mx = aval;
#pragma unroll
    for (int s = 16; s; s >>= 1) mx = fmaxf(mx, __shfl_xor_sync(0xffffffffu, mx, s));
    const float e = __expf(aval - mx);
    float sm = e;
#pragma unroll
    for (int s = 16; s; s >>= 1) sm += __shfl_xor_sync(0xffffffffu, sm, s);
    const float aw = e / sm;

    {
        const int j  = lane;
        const int lv = j >> 3;
        const int Wl = cWL[lv], Hl = cHL[lv];

        const float2 o2 = *(const float2*)(g_qo + (size_t)bq * 768 + 256
                                           + h * 64 + j * 2);
        const float rx = refp[(size_t)bq * 8 + lv * 2];
        const float ry = refp[(size_t)bq * 8 + lv * 2 + 1];

        const float locx = rx + o2.x * cIW[lv];
        const float locy = ry + o2.y * cIH[lv];
        const float gx = 2.f * locx - 1.f;
        const float gy = 2.f * locy - 1.f;
        const float x = (gx + 1.f) * ((float)Wl * 0.5f) - 0.5f;
        const float y = (gy + 1.f) * ((float)Hl * 0.5f) - 0.5f;

        const float xf = floorf(x), yf = floorf(y);
        const float wx = x - xf,    wy = y - yf;
        const int x0 = (int)xf, y0 = (int)yf;
        const int x1 = x0 + 1,  y1 = y0 + 1;

        const bool vx0 = (x0 >= 0) && (x0 < Wl);
        const bool vx1 = (x1 >= 0) && (x1 < Wl);
        const bool vy0 = (y0 >= 0) && (y0 < Hl);
        const bool vy1 = (y1 >= 0) && (y1 < Hl);

        const int xA = min(max(x0, 0), Wl - 1);
        const int xB = min(max(x1, 0), Wl - 1);
        const int yA = min(max(y0, 0), Hl - 1);
        const int yB = min(max(y1, 0), Hl - 1);

        // byte offsets within this head's plane: 64 B per location
        const int base = cST[lv];
        const int off00 = (base + yA * Wl + xA) << 6;
        const int off10 = (base + yA * Wl + xB) << 6;
        const int off01 = (base + yB * Wl + xA) << 6;
        const int off11 = (base + yB * Wl + xB) << 6;

        const float w00 = (vx0 && vy0) ? aw * (1.f - wx) * (1.f - wy) : 0.f;
        const float w10 = (vx1 && vy0) ? aw * wx         * (1.f - wy) : 0.f;
        const float w01 = (vx0 && vy1) ? aw * (1.f - wx) * wy         : 0.f;
        const float w11 = (vx1 && vy1) ? aw * wx         * wy         : 0.f;

        st[h][0][j] = make_float2(__int_as_float(off00), w00);
        st[h][1][j] = make_float2(__int_as_float(off10), w10);
        st[h][2][j] = make_float2(__int_as_float(off01), w01);
        st[h][3][j] = make_float2(__int_as_float(off11), w11);
    }
    __syncwarp();

    const int g  = lane >> 3;
    const int cq = lane & 7;
    const char* vb = (const char*)(g_v
        + (((size_t)(b * NH + h) * LTOT) << 5) + cq * 4);
    const float2* owrow = st[h][g];

    float4 acc = make_float4(0.f, 0.f, 0.f, 0.f);
#pragma unroll 4
    for (int p = 0; p < 32; p += 2) {
        const float4 ow2 = *(const float4*)(owrow + p);
        const uint2 ua = *(const uint2*)(vb + __float_as_int(ow2.x));
        const uint2 ub = *(const uint2*)(vb + __float_as_int(ow2.z));
        const float2 a01 = __half22float2(*(const __half2*)&ua.x);
        const float2 a23 = __half22float2(*(const __half2*)&ua.y);
        const float2 b01 = __half22float2(*(const __half2*)&ub.x);
        const float2 b23 = __half22float2(*(const __half2*)&ub.y);
        acc.x = fmaf(ow2.y, a01.x, acc.x);
        acc.y = fmaf(ow2.y, a01.y, acc.y);
        acc.z = fmaf(ow2.y, a23.x, acc.z);
        acc.w = fmaf(ow2.y, a23.y, acc.w);
        acc.x = fmaf(ow2.w, b01.x, acc.x);
        acc.y = fmaf(ow2.w, b01.y, acc.y);
        acc.z = fmaf(ow2.w, b23.x, acc.z);
        acc.w = fmaf(ow2.w, b23.y, acc.w);
    }
#pragma unroll
    for (int s = 8; s <= 16; s <<= 1) {
        acc.x += __shfl_xor_sync(0xffffffffu, acc.x, s);
        acc.y += __shfl_xor_sync(0xffffffffu, acc.y, s);
        acc.z += __shfl_xor_sync(0xffffffffu, acc.z, s);
        acc.w += __shfl_xor_sync(0xffffffffu, acc.w, s);
    }
    if (g == 0)
        *(float4*)(g_tmp + (size_t)bq * EMB + h * 32 + cq * 4) = acc;
}

// ---------------- launch ---------------------------------------------------
extern "C" void kernel_launch(void* const* d_in, const int* in_sizes, int n_in,
                              void* d_out, int out_size)
{
    const float* query  = (const float*)d_in[0];
    const float* value  = (const float*)d_in[1];
    const float* refp   = (const float*)d_in[2];
    const float* W_off  = (const float*)d_in[4];
    const float* b_off  = (const float*)d_in[5];
    const float* W_attn = (const float*)d_in[6];
    const float* b_attn = (const float*)d_in[7];
    const float* W_val  = (const float*)d_in[8];
    const float* b_val  = (const float*)d_in[9];
    const float* W_out  = (const float*)d_in[10];
    const float* b_out  = (const float*)d_in[11];
    float* out = (float*)d_out;

    float *gqo, *gtmp, *gbqo;
    __half* gv;
    __nv_bfloat16 *wth, *wtl;
    cudaGetSymbolAddress((void**)&gv,   g_v);
    cudaGetSymbolAddress((void**)&gqo,  g_qo);
    cudaGetSymbolAddress((void**)&gtmp, g_tmp);
    cudaGetSymbolAddress((void**)&gbqo, g_bqo);
    cudaGetSymbolAddress((void**)&wth,  g_wt_hi);
    cudaGetSymbolAddress((void**)&wtl,  g_wt_lo);

    cudaFuncSetAttribute(gemm_vq_kernel,
                         cudaFuncAttributeMaxDynamicSharedMemorySize, SMEM_DYN);
    cudaFuncSetAttribute(gemm_out_kernel,
                         cudaFuncAttributeMaxDynamicSharedMemorySize, SMEM_DYN);

    // 0) weight transpose + bf16 hi/lo split + fused bias
    prep_weights<<<1280, 256>>>(W_val, W_attn, W_off, W_out, b_attn, b_off);

    // 1) fused: value projection (fp16, head-split) -> g_v  AND  attn+off -> g_qo
    gemm_vq_kernel<<<NVB + 6 * (MQ / 64), 128, SMEM_DYN>>>(
        value, query, wth, wtl, b_val, gbqo, gv, gqo);

    // 2) softmax + bilinear sampling -> g_tmp
    msda_sample_kernel<<<MQ, dim3(32, 8)>>>(refp);

    // 3) output projection -> d_out
    gemm_out_kernel<<<dim3(2, MQ / 64), 128, SMEM_DYN>>>(
        gtmp, wth, wtl, b_out, out);
}

// round 15
// speedup vs baseline: 1.4306x; 1.1429x over previous
#include <cuda_runtime.h>
#include <cuda_bf16.h>
#include <cuda_fp16.h>
#include <cstdint>

// ---------------- problem constants ----------------
#define BS   6
#define NQ   4096
#define EMB  256
#define NH   8
#define LTOT 19560            // 92*160 + 46*80 + 23*40 + 12*20
#define MQ   (BS * NQ)        // 24576
#define MV   (BS * LTOT)      // 117360
#define KDIM 256

// ---------------- scratch (device globals; no cudaMalloc allowed) ----------
// g_v layout: [b][head][location][32 ch] fp16  (64 B per (head,loc))
__device__ __half g_v [(size_t)MV * EMB];
__device__ float g_qo [(size_t)MQ * 768];    // [attn 256 | off 512] per row
__device__ float g_tmp[(size_t)MQ * EMB];
__device__ float g_bqo[768];                 // fused bias [b_attn | b_off]

// qo weights: transposed + bf16 hi/lo split; rows = out col n (768 rows)
__device__ __align__(128) __nv_bfloat16 g_wt_hi[768 * 256];
__device__ __align__(128) __nv_bfloat16 g_wt_lo[768 * 256];
// val + out weights: transposed, fp16 single; [val 256 | out 256] rows
__device__ __align__(128) __half g_w16[512 * 256];
#define W16_VAL 0
#define W16_OUT 256

__constant__ int   cHL[4] = {92, 46, 23, 12};
__constant__ int   cWL[4] = {160, 80, 40, 20};
__constant__ int   cST[4] = {0, 14720, 18400, 19320};
__constant__ float cIW[4] = {1.f/160.f, 1.f/80.f, 1.f/40.f, 1.f/20.f};
__constant__ float cIH[4] = {1.f/92.f,  1.f/46.f, 1.f/23.f, 1.f/12.f};

// ---------------- helpers ---------------------------------------------------
__device__ __forceinline__ uint32_t smem_u32(const void* p) {
    uint32_t a;
    asm("{ .reg .u64 t; cvta.to.shared.u64 t, %1; cvt.u32.u64 %0, t; }"
        : "=r"(a) : "l"(p));
    return a;
}
__device__ __forceinline__ void ldsm_x4(uint32_t* r, uint32_t addr) {
    asm volatile("ldmatrix.sync.aligned.m8n8.x4.shared.b16 {%0,%1,%2,%3}, [%4];"
                 : "=r"(r[0]), "=r"(r[1]), "=r"(r[2]), "=r"(r[3]) : "r"(addr));
}
__device__ __forceinline__ void mma_bf16(float* c, const uint32_t* a,
                                         const uint32_t* b) {
    asm volatile(
        "mma.sync.aligned.m16n8k16.row.col.f32.bf16.bf16.f32 "
        "{%0,%1,%2,%3}, {%4,%5,%6,%7}, {%8,%9}, {%0,%1,%2,%3};"
        : "+f"(c[0]), "+f"(c[1]), "+f"(c[2]), "+f"(c[3])
        : "r"(a[0]), "r"(a[1]), "r"(a[2]), "r"(a[3]), "r"(b[0]), "r"(b[1]));
}
__device__ __forceinline__ void mma_f16(float* c, const uint32_t* a,
                                        const uint32_t* b) {
    asm volatile(
        "mma.sync.aligned.m16n8k16.row.col.f32.f16.f16.f32 "
        "{%0,%1,%2,%3}, {%4,%5,%6,%7}, {%8,%9}, {%0,%1,%2,%3};"
        : "+f"(c[0]), "+f"(c[1]), "+f"(c[2]), "+f"(c[3])
        : "r"(a[0]), "r"(a[1]), "r"(a[2]), "r"(a[3]), "r"(b[0]), "r"(b[1]));
}
__device__ __forceinline__ void cp16(uint32_t dst, const void* src) {
    asm volatile("cp.async.cg.shared.global [%0], [%1], 16;"
                 :: "r"(dst), "l"(src) : "memory");
}
#define CP_COMMIT() asm volatile("cp.async.commit_group;" ::: "memory")
#define CP_WAIT(n)  asm volatile("cp.async.wait_group " #n ";" ::: "memory")

// ---------------- weight prep -----------------------------------------------
// blocks 0..767: qo weights (attn 256 | off 512) -> bf16 hi/lo transposed
// blocks 768..1023: val weights -> fp16 transposed
// blocks 1024..1279: out weights -> fp16 transposed
__global__ void prep_weights(const float* __restrict__ Wv,
                             const float* __restrict__ Wa,
                             const float* __restrict__ Wf,
                             const float* __restrict__ Wo,
                             const float* __restrict__ ba,
                             const float* __restrict__ bf)
{
    const int n = blockIdx.x;
    const int k = threadIdx.x;
    if (n == 0) g_bqo[k]       = ba[k];
    if (n == 1) g_bqo[256 + k] = bf[k];
    if (n == 2) g_bqo[512 + k] = bf[256 + k];

    if (n < 768) {               // qo: attn rows 0..255, off rows 256..767
        const float* W; int N, row;
        if (n < 256) { W = Wa; N = 256; row = n;       }
        else         { W = Wf; N = 512; row = n - 256; }
        const float w = W[(size_t)k * N + row];
        const __nv_bfloat16 h = __float2bfloat16(w);
        g_wt_hi[(size_t)n * 256 + k] = h;
        g_wt_lo[(size_t)n * 256 + k] = __float2bfloat16(w - __bfloat162float(h));
    } else {
        const float* W; int row;
        if (n < 1024) { W = Wv; row = n - 768;  }
        else          { W = Wo; row = n - 1024; }
        const float w = W[(size_t)k * 256 + row];
        g_w16[(size_t)(n - 768) * 256 + k] = __float2half(w);
    }
}

// ---------------- shared GEMM geometry --------------------------------------
// tile 64x128, kb=32, 2-stage cp.async, 128 threads (4 warps 2x2).
#define AROW  160
#define S_A   0
// bf16x3 layout
#define S_BHI 10240
#define S_BLO 18432
#define STGB  26624
#define SMEM_B3 (2 * STGB)         // 53248 B
// fp16x2 layout
#define S_BH  10240
#define STGH  18432
#define SMEM_H2 (2 * STGH)         // 36864 B
#define SMEM_DYN SMEM_B3           // vq kernel hosts both paths

// ---------------- bf16x3 core (qo GEMM) -------------------------------------
__device__ __forceinline__ void gemm_core_b3(
    const float* __restrict__ A,
    const __nv_bfloat16* __restrict__ BtHi,
    const __nv_bfloat16* __restrict__ BtLo,
    const float* __restrict__ bias,
    float* __restrict__ C, int M, int N, int bx, int by, char* sp)
{
    const uint32_t s0 = smem_u32(sp);
    const int tid  = threadIdx.x;
    const int wid  = tid >> 5;
    const int lane = tid & 31;
    const int wm   = wid >> 1;
    const int wn   = wid & 1;
    const int row0 = by * 64;
    const int col0 = bx * 128;

    const int q   = lane >> 2;
    const int t2  = (lane & 3) * 2;
    const int lrB = (lane & 7) + (lane >> 4) * 8;
    const int lkB = ((lane >> 3) & 1) * 8;

    float acc[2][8][4];
#pragma unroll
    for (int mt = 0; mt < 2; ++mt)
#pragma unroll
        for (int nt = 0; nt < 8; ++nt)
#pragma unroll
            for (int i = 0; i < 4; ++i) acc[mt][nt][i] = 0.f;

    auto load_kb = [&](int kb, int st) {
        const uint32_t sb = s0 + st * STGB;
#pragma unroll
        for (int it = 0; it < 4; ++it) {
            const int chunk = it * 128 + tid;
            const int row = chunk >> 3, c = chunk & 7;
            const int gr  = row0 + row;
            const int vr  = (gr < M) ? gr : 0;
            cp16(sb + S_A + row * AROW + c * 16,
                 A + (size_t)vr * KDIM + kb * 32 + c * 4);
        }
#pragma unroll
        for (int it = 0; it < 8; ++it) {
            const int chunk = it * 128 + tid;
            const int half = chunk >> 9;
            const int rc = chunk & 511;
            const int r = rc >> 2, c = rc & 3;
            const int csw = c ^ ((r >> 1) & 3);
            const __nv_bfloat16* src = (half ? BtLo : BtHi)
                                     + (size_t)(col0 + r) * KDIM + kb * 32 + c * 8;
            cp16(sb + (half ? S_BLO : S_BHI) + r * 64 + csw * 16, src);
        }
    };

    load_kb(0, 0);
    CP_COMMIT();

    int s = 0;
    for (int kb = 0; kb < 8; ++kb) {
        if (kb < 7) {
            load_kb(kb + 1, s ^ 1);
            CP_COMMIT();
            CP_WAIT(1);
        } else {
            CP_WAIT(0);
        }
        __syncthreads();

        const char*    spA = sp + s * STGB + S_A;
        const uint32_t sbB = s0 + s * STGB;

#pragma unroll
        for (int ks = 0; ks < 2; ++ks) {
            const int k0 = ks * 16;
            uint32_t ahi[2][4], alo[2][4];
#pragma unroll
            for (int mt = 0; mt < 2; ++mt) {
                const int rb = wm * 32 + mt * 16 + q;
#pragma unroll
                for (int i = 0; i < 4; ++i) {
                    const int r = rb + (i & 1) * 8;
                    const int k = k0 + t2 + (i >> 1) * 8;
                    const float2 f = *(const float2*)(spA + r * AROW + k * 4);
                    __nv_bfloat162 h2 = __floats2bfloat162_rn(f.x, f.y);
                    const uint32_t h = *reinterpret_cast<uint32_t*>(&h2);
                    const float g0 = __uint_as_float(h << 16);
                    const float g1 = __uint_as_float(h & 0xFFFF0000u);
                    __nv_bfloat162 l2 = __floats2bfloat162_rn(f.x - g0, f.y - g1);
                    ahi[mt][i] = h;
                    alo[mt][i] = *reinterpret_cast<uint32_t*>(&l2);
                }
            }
            const int ck = (k0 + lkB) >> 3;
#pragma unroll
            for (int np = 0; np < 4; ++np) {
                const int n = wn * 64 + np * 16 + lrB;
                const uint32_t boff = (uint32_t)(n * 64
                                      + ((ck ^ ((n >> 1) & 3)) << 4));
                uint32_t bh[4], bl[4];
                ldsm_x4(bh, sbB + S_BHI + boff);
                ldsm_x4(bl, sbB + S_BLO + boff);
#pragma unroll
                for (int mt = 0; mt < 2; ++mt) {
#pragma unroll
                    for (int h2 = 0; h2 < 2; ++h2) {
                        float* c = acc[mt][np * 2 + h2];
                        mma_bf16(c, ahi[mt], bh + h2 * 2);
                        mma_bf16(c, ahi[mt], bl + h2 * 2);
                        mma_bf16(c, alo[mt], bh + h2 * 2);
                    }
                }
            }
        }
        __syncthreads();
        s ^= 1;
    }

    const int n2 = (lane & 3) * 2;
#pragma unroll
    for (int mt = 0; mt < 2; ++mt) {
        const int mbase = row0 + wm * 32 + mt * 16 + q;
#pragma unroll
        for (int nt = 0; nt < 8; ++nt) {
            const int gc = col0 + wn * 64 + nt * 8 + n2;
            const float bx2 = bias[gc], by2 = bias[gc + 1];
            const float* c = acc[mt][nt];
#pragma unroll
            for (int half = 0; half < 2; ++half) {
                const int m = mbase + half * 8;
                if (m < M)
                    *(float2*)(C + (size_t)m * N + gc) =
                        make_float2(c[half * 2 + 0] + bx2,
                                    c[half * 2 + 1] + by2);
            }
        }
    }
}

// ---------------- fp16x2 core (val / out GEMMs) -----------------------------
// C = A * Bh^T (Bh = fp16-rounded weights); 2 terms Ahi*Bh + Alo*Bh.
template <typename OutT, bool HSPLIT>
__device__ __forceinline__ void gemm_core_h2(
    const float* __restrict__ A,
    const __half* __restrict__ Bt,
    const float* __restrict__ bias,
    OutT* __restrict__ C, int M, int N, int bx, int by, char* sp)
{
    const uint32_t s0 = smem_u32(sp);
    const int tid  = threadIdx.x;
    const int wid  = tid >> 5;
    const int lane = tid & 31;
    const int wm   = wid >> 1;
    const int wn   = wid & 1;
    const int row0 = by * 64;
    const int col0 = bx * 128;

    const int q   = lane >> 2;
    const int t2  = (lane & 3) * 2;
    const int lrB = (lane & 7) + (lane >> 4) * 8;
    const int lkB = ((lane >> 3) & 1) * 8;

    float acc[2][8][4];
#pragma unroll
    for (int mt = 0; mt < 2; ++mt)
#pragma unroll
        for (int nt = 0; nt < 8; ++nt)
#pragma unroll
            for (int i = 0; i < 4; ++i) acc[mt][nt][i] = 0.f;

    auto load_kb = [&](int kb, int st) {
        const uint32_t sb = s0 + st * STGH;
#pragma unroll
        for (int it = 0; it < 4; ++it) {
            const int chunk = it * 128 + tid;
            const int row = chunk >> 3, c = chunk & 7;
            const int gr  = row0 + row;
            const int vr  = (gr < M) ? gr : 0;
            cp16(sb + S_A + row * AROW + c * 16,
                 A + (size_t)vr * KDIM + kb * 32 + c * 4);
        }
        // B: 128 rows x 32 fp16 (64B), 512 chunks, 4/thread, XOR swizzle
#pragma unroll
        for (int it = 0; it < 4; ++it) {
            const int chunk = it * 128 + tid;
            const int r = chunk >> 2, c = chunk & 3;
            const int csw = c ^ ((r >> 1) & 3);
            cp16(sb + S_BH + r * 64 + csw * 16,
                 Bt + (size_t)(col0 + r) * KDIM + kb * 32 + c * 8);
        }
    };

    load_kb(0, 0);
    CP_COMMIT();

    int s = 0;
    for (int kb = 0; kb < 8; ++kb) {
        if (kb < 7) {
            load_kb(kb + 1, s ^ 1);
            CP_COMMIT();
            CP_WAIT(1);
        } else {
            CP_WAIT(0);
        }
        __syncthreads();

        const char*    spA = sp + s * STGH + S_A;
        const uint32_t sbB = s0 + s * STGH;

#pragma unroll
        for (int ks = 0; ks < 2; ++ks) {
            const int k0 = ks * 16;
            uint32_t ahi[2][4], alo[2][4];
#pragma unroll
            for (int mt = 0; mt < 2; ++mt) {
                const int rb = wm * 32 + mt * 16 + q;
#pragma unroll
                for (int i = 0; i < 4; ++i) {
                    const int r = rb + (i & 1) * 8;
                    const int k = k0 + t2 + (i >> 1) * 8;
                    const float2 f = *(const float2*)(spA + r * AROW + k * 4);
                    const __half2 h2 = __floats2half2_rn(f.x, f.y);
                    const float2 hf = __half22float2(h2);
                    const __half2 l2 = __floats2half2_rn(f.x - hf.x, f.y - hf.y);
                    ahi[mt][i] = *reinterpret_cast<const uint32_t*>(&h2);
                    alo[mt][i] = *reinterpret_cast<const uint32_t*>(&l2);
                }
            }
            const int ck = (k0 + lkB) >> 3;
#pragma unroll
            for (int np = 0; np < 4; ++np) {
                const int n = wn * 64 + np * 16 + lrB;
                const uint32_t boff = (uint32_t)(n * 64
                                      + ((ck ^ ((n >> 1) & 3)) << 4));
                uint32_t bh[4];
                ldsm_x4(bh, sbB + S_BH + boff);
#pragma unroll
                for (int mt = 0; mt < 2; ++mt) {
#pragma unroll
                    for (int h2 = 0; h2 < 2; ++h2) {
                        float* c = acc[mt][np * 2 + h2];
                        mma_f16(c, ahi[mt], bh + h2 * 2);
                        mma_f16(c, alo[mt], bh + h2 * 2);
                    }
                }
            }
        }
        __syncthreads();
        s ^= 1;
    }

    const int n2 = (lane & 3) * 2;
#pragma unroll
    for (int mt = 0; mt < 2; ++mt) {
        const int mbase = row0 + wm * 32 + mt * 16 + q;
#pragma unroll
        for (int nt = 0; nt < 8; ++nt) {
            const int gc = col0 + wn * 64 + nt * 8 + n2;
            const float bx2 = bias[gc], by2 = bias[gc + 1];
            const float* c = acc[mt][nt];
#pragma unroll
            for (int half = 0; half < 2; ++half) {
                const int m = mbase + half * 8;
                if (m < M) {
                    if constexpr (HSPLIT) {
                        const int b   = m / LTOT;
                        const int loc = m - b * LTOT;
                        const int hh  = gc >> 5;
                        const int ch  = gc & 31;
                        const size_t addr =
                            (((size_t)(b * NH + hh) * LTOT + loc) << 5) + ch;
                        *(__half2*)((__half*)C + addr) =
                            __floats2half2_rn(c[half * 2 + 0] + bx2,
                                              c[half * 2 + 1] + by2);
                    } else {
                        *(float2*)((float*)C + (size_t)m * N + gc) =
                            make_float2(c[half * 2 + 0] + bx2,
                                        c[half * 2 + 1] + by2);
                    }
                }
            }
        }
    }
}

// fused val + qo GEMMs in one launch (linearized grid)
#define NVB (2 * 1834)            // val blocks: x=2, y=1834
__global__ __launch_bounds__(128, 4)
void gemm_vq_kernel(const float* __restrict__ Aval,
                    const float* __restrict__ Aqry,
                    const __half* __restrict__ w16,
                    const __nv_bfloat16* __restrict__ wth,
                    const __nv_bfloat16* __restrict__ wtl,
                    const float* __restrict__ bval,
                    const float* __restrict__ bqo,
                    __half* __restrict__ Cval, float* __restrict__ Cqo)
{
    extern __shared__ __align__(16) char sp[];
    const int bid = blockIdx.x;
    if (bid < NVB) {
        gemm_core_h2<__half, true>(Aval, w16 + (size_t)W16_VAL * 256,
                                   bval, Cval, MV, 256, bid & 1, bid >> 1, sp);
    } else {
        const int r = bid - NVB;
        gemm_core_b3(Aqry, wth, wtl, bqo, Cqo, MQ, 768, r % 6, r / 6, sp);
    }
}

__global__ __launch_bounds__(128, 4)
void gemm_out_kernel(const float* __restrict__ A,
                     const __half* __restrict__ w16,
                     const float* __restrict__ bias,
                     float* __restrict__ C)
{
    extern __shared__ __align__(16) char sp[];
    gemm_core_h2<float, false>(A, w16 + (size_t)W16_OUT * 256,
                               bias, C, MQ, 256, blockIdx.x, blockIdx.y, sp);
}

// ---------------- deformable sampling core --------------------------------
// g_v is head-split: [b][head][loc][32ch fp16] -> 64 B per (head,loc).
__global__ __launch_bounds__(256)
void msda_sample_kernel(const float* __restrict__ refp)
{
    __shared__ float2 st[NH][4][36];     // [head][corner][point(+pad)]

    const int bq   = blockIdx.x;
    const int lane = threadIdx.x;
    const int h    = threadIdx.y;
    const int b    = bq >> 12;

    const float aval = g_qo[(size_t)bq * 768 + h * 32 + lane];
    float mx = aval;
#pragma unroll
    for (int s = 16; s; s >>= 1) mx = fmaxf(mx, __shfl_xor_sync(0xffffffffu, mx, s));
    const float e = __expf(aval - mx);
    float sm = e;
#pragma unroll
    for (int s = 16; s; s >>= 1) sm += __shfl_xor_sync(0xffffffffu, sm, s);
    const float aw = e / sm;

    {
        const int j  = lane;
        const int lv = j >> 3;
        const int Wl = cWL[lv], Hl = cHL[lv];

        const float2 o2 = *(const float2*)(g_qo + (size_t)bq * 768 + 256
                                           + h * 64 + j * 2);
        const float rx = refp[(size_t)bq * 8 + lv * 2];
        const float ry = refp[(size_t)bq * 8 + lv * 2 + 1];

        const float locx = rx + o2.x * cIW[lv];
        const float locy = ry + o2.y * cIH[lv];
        const float gx = 2.f * locx - 1.f;
        const float gy = 2.f * locy - 1.f;
        const float x = (gx + 1.f) * ((float)Wl * 0.5f) - 0.5f;
        const float y = (gy + 1.f) * ((float)Hl * 0.5f) - 0.5f;

        const float xf = floorf(x), yf = floorf(y);
        const float wx = x - xf,    wy = y - yf;
        const int x0 = (int)xf, y0 = (int)yf;
        const int x1 = x0 + 1,  y1 = y0 + 1;

        const bool vx0 = (x0 >= 0) && (x0 < Wl);
        const bool vx1 = (x1 >= 0) && (x1 < Wl);
        const bool vy0 = (y0 >= 0) && (y0 < Hl);
        const bool vy1 = (y1 >= 0) && (y1 < Hl);

        const int xA = min(max(x0, 0), Wl - 1);
        const int xB = min(max(x1, 0), Wl - 1);
        const int yA = min(max(y0, 0), Hl - 1);
        const int yB = min(max(y1, 0), Hl - 1);

        const int base = cST[lv];
        const int off00 = (base + yA * Wl + xA) << 6;
        const int off10 = (base + yA * Wl + xB) << 6;
        const int off01 = (base + yB * Wl + xA) << 6;
        const int off11 = (base + yB * Wl + xB) << 6;

        const float w00 = (vx0 && vy0) ? aw * (1.f - wx) * (1.f - wy) : 0.f;
        const float w10 = (vx1 && vy0) ? aw * wx         * (1.f - wy) : 0.f;
        const float w01 = (vx0 && vy1) ? aw * (1.f - wx) * wy         : 0.f;
        const float w11 = (vx1 && vy1) ? aw * wx         * wy         : 0.f;

        st[h][0][j] = make_float2(__int_as_float(off00), w00);
        st[h][1][j] = make_float2(__int_as_float(off10), w10);
        st[h][2][j] = make_float2(__int_as_float(off01), w01);
        st[h][3][j] = make_float2(__int_as_float(off11), w11);
    }
    __syncwarp();

    const int g  = lane >> 3;
    const int cq = lane & 7;
    const char* vb = (const char*)(g_v
        + (((size_t)(b * NH + h) * LTOT) << 5) + cq * 4);
    const float2* owrow = st[h][g];

    float4 acc = make_float4(0.f, 0.f, 0.f, 0.f);
#pragma unroll 4
    for (int p = 0; p < 32; p += 2) {
        const float4 ow2 = *(const float4*)(owrow + p);
        const uint2 ua = *(const uint2*)(vb + __float_as_int(ow2.x));
        const uint2 ub = *(const uint2*)(vb + __float_as_int(ow2.z));
        const float2 a01 = __half22float2(*(const __half2*)&ua.x);
        const float2 a23 = __half22float2(*(const __half2*)&ua.y);
        const float2 b01 = __half22float2(*(const __half2*)&ub.x);
        const float2 b23 = __half22float2(*(const __half2*)&ub.y);
        acc.x = fmaf(ow2.y, a01.x, acc.x);
        acc.y = fmaf(ow2.y, a01.y, acc.y);
        acc.z = fmaf(ow2.y, a23.x, acc.z);
        acc.w = fmaf(ow2.y, a23.y, acc.w);
        acc.x = fmaf(ow2.w, b01.x, acc.x);
        acc.y = fmaf(ow2.w, b01.y, acc.y);
        acc.z = fmaf(ow2.w, b23.x, acc.z);
        acc.w = fmaf(ow2.w, b23.y, acc.w);
    }
#pragma unroll
    for (int s = 8; s <= 16; s <<= 1) {
        acc.x += __shfl_xor_sync(0xffffffffu, acc.x, s);
        acc.y += __shfl_xor_sync(0xffffffffu, acc.y, s);
        acc.z += __shfl_xor_sync(0xffffffffu, acc.z, s);
        acc.w += __shfl_xor_sync(0xffffffffu, acc.w, s);
    }
    if (g == 0)
        *(float4*)(g_tmp + (size_t)bq * EMB + h * 32 + cq * 4) = acc;
}

// ---------------- launch ---------------------------------------------------
extern "C" void kernel_launch(void* const* d_in, const int* in_sizes, int n_in,
                              void* d_out, int out_size)
{
    const float* query  = (const float*)d_in[0];
    const float* value  = (const float*)d_in[1];
    const float* refp   = (const float*)d_in[2];
    const float* W_off  = (const float*)d_in[4];
    const float* b_off  = (const float*)d_in[5];
    const float* W_attn = (const float*)d_in[6];
    const float* b_attn = (const float*)d_in[7];
    const float* W_val  = (const float*)d_in[8];
    const float* b_val  = (const float*)d_in[9];
    const float* W_out  = (const float*)d_in[10];
    const float* b_out  = (const float*)d_in[11];
    float* out = (float*)d_out;

    float *gqo, *gtmp, *gbqo;
    __half *gv, *gw16;
    __nv_bfloat16 *wth, *wtl;
    cudaGetSymbolAddress((void**)&gv,   g_v);
    cudaGetSymbolAddress((void**)&gqo,  g_qo);
    cudaGetSymbolAddress((void**)&gtmp, g_tmp);
    cudaGetSymbolAddress((void**)&gbqo, g_bqo);
    cudaGetSymbolAddress((void**)&gw16, g_w16);
    cudaGetSymbolAddress((void**)&wth,  g_wt_hi);
    cudaGetSymbolAddress((void**)&wtl,  g_wt_lo);

    cudaFuncSetAttribute(gemm_vq_kernel,
                         cudaFuncAttributeMaxDynamicSharedMemorySize, SMEM_DYN);
    cudaFuncSetAttribute(gemm_out_kernel,
                         cudaFuncAttributeMaxDynamicSharedMemorySize, SMEM_H2);

    // 0) weight prep
    prep_weights<<<1280, 256>>>(W_val, W_attn, W_off, W_out, b_attn, b_off);

    // 1) fused: value projection (fp16x2, head-split) -> g_v  AND  qo -> g_qo
    gemm_vq_kernel<<<NVB + 6 * (MQ / 64), 128, SMEM_DYN>>>(
        value, query, gw16, wth, wtl, b_val, gbqo, gv, gqo);

    // 2) softmax + bilinear sampling -> g_tmp
    msda_sample_kernel<<<MQ, dim3(32, 8)>>>(refp);

    // 3) output projection (fp16x2) -> d_out
    gemm_out_kernel<<<dim3(2, MQ / 64), 128, SMEM_H2>>>(
        gtmp, gw16, b_out, out);
}

// round 16
// speedup vs baseline: 1.5758x; 1.1015x over previous
#include <cuda_runtime.h>
#include <cuda_bf16.h>
#include <cuda_fp16.h>
#include <cstdint>

// ---------------- problem constants ----------------
#define BS   6
#define NQ   4096
#define EMB  256
#define NH   8
#define LTOT 19560            // 92*160 + 46*80 + 23*40 + 12*20
#define MQ   (BS * NQ)        // 24576
#define MV   (BS * LTOT)      // 117360
#define KDIM 256

// ---------------- scratch (device globals; no cudaMalloc allowed) ----------
// g_v layout: [b][head][location][32 ch] fp16  (64 B per (head,loc))
__device__ __half g_v [(size_t)MV * EMB];
__device__ float g_qo [(size_t)MQ * 768];    // [attn 256 | off 512] per row
__device__ float g_tmp[(size_t)MQ * EMB];
__device__ float g_bqo[768];                 // fused bias [b_attn | b_off]

// qo weights: transposed + bf16 hi/lo split; rows = out col n (768 rows)
__device__ __align__(128) __nv_bfloat16 g_wt_hi[768 * 256];
__device__ __align__(128) __nv_bfloat16 g_wt_lo[768 * 256];
// val + out weights: transposed, fp16 single; [val 256 | out 256] rows
__device__ __align__(128) __half g_w16[512 * 256];
#define W16_VAL 0
#define W16_OUT 256

__constant__ int   cHL[4] = {92, 46, 23, 12};
__constant__ int   cWL[4] = {160, 80, 40, 20};
__constant__ int   cST[4] = {0, 14720, 18400, 19320};
__constant__ float cIW[4] = {1.f/160.f, 1.f/80.f, 1.f/40.f, 1.f/20.f};
__constant__ float cIH[4] = {1.f/92.f,  1.f/46.f, 1.f/23.f, 1.f/12.f};

// ---------------- helpers ---------------------------------------------------
__device__ __forceinline__ uint32_t smem_u32(const void* p) {
    uint32_t a;
    asm("{ .reg .u64 t; cvta.to.shared.u64 t, %1; cvt.u32.u64 %0, t; }"
        : "=r"(a) : "l"(p));
    return a;
}
__device__ __forceinline__ void ldsm_x4(uint32_t* r, uint32_t addr) {
    asm volatile("ldmatrix.sync.aligned.m8n8.x4.shared.b16 {%0,%1,%2,%3}, [%4];"
                 : "=r"(r[0]), "=r"(r[1]), "=r"(r[2]), "=r"(r[3]) : "r"(addr));
}
__device__ __forceinline__ void mma_bf16(float* c, const uint32_t* a,
                                         const uint32_t* b) {
    asm volatile(
        "mma.sync.aligned.m16n8k16.row.col.f32.bf16.bf16.f32 "
        "{%0,%1,%2,%3}, {%4,%5,%6,%7}, {%8,%9}, {%0,%1,%2,%3};"
        : "+f"(c[0]), "+f"(c[1]), "+f"(c[2]), "+f"(c[3])
        : "r"(a[0]), "r"(a[1]), "r"(a[2]), "r"(a[3]), "r"(b[0]), "r"(b[1]));
}
__device__ __forceinline__ void mma_f16(float* c, const uint32_t* a,
                                        const uint32_t* b) {
    asm volatile(
        "mma.sync.aligned.m16n8k16.row.col.f32.f16.f16.f32 "
        "{%0,%1,%2,%3}, {%4,%5,%6,%7}, {%8,%9}, {%0,%1,%2,%3};"
        : "+f"(c[0]), "+f"(c[1]), "+f"(c[2]), "+f"(c[3])
        : "r"(a[0]), "r"(a[1]), "r"(a[2]), "r"(a[3]), "r"(b[0]), "r"(b[1]));
}
__device__ __forceinline__ void cp16(uint32_t dst, const void* src) {
    asm volatile("cp.async.cg.shared.global [%0], [%1], 16;"
                 :: "r"(dst), "l"(src) : "memory");
}
#define CP_COMMIT() asm volatile("cp.async.commit_group;" ::: "memory")
#define CP_WAIT(n)  asm volatile("cp.async.wait_group " #n ";" ::: "memory")

// ---------------- weight prep -----------------------------------------------
__global__ void prep_weights(const float* __restrict__ Wv,
                             const float* __restrict__ Wa,
                             const float* __restrict__ Wf,
                             const float* __restrict__ Wo,
                             const float* __restrict__ ba,
                             const float* __restrict__ bf)
{
    const int n = blockIdx.x;
    const int k = threadIdx.x;
    if (n == 0) g_bqo[k]       = ba[k];
    if (n == 1) g_bqo[256 + k] = bf[k];
    if (n == 2) g_bqo[512 + k] = bf[256 + k];

    if (n < 768) {               // qo: attn rows 0..255, off rows 256..767
        const float* W; int N, row;
        if (n < 256) { W = Wa; N = 256; row = n;       }
        else         { W = Wf; N = 512; row = n - 256; }
        const float w = W[(size_t)k * N + row];
        const __nv_bfloat16 h = __float2bfloat16(w);
        g_wt_hi[(size_t)n * 256 + k] = h;
        g_wt_lo[(size_t)n * 256 + k] = __float2bfloat16(w - __bfloat162float(h));
    } else {
        const float* W; int row;
        if (n < 1024) { W = Wv; row = n - 768;  }
        else          { W = Wo; row = n - 1024; }
        const float w = W[(size_t)k * 256 + row];
        g_w16[(size_t)(n - 768) * 256 + k] = __float2half(w);
    }
}

// ---------------- shared GEMM geometry --------------------------------------
// tile 64x128, kb=32, 2-stage cp.async, 128 threads (4 warps 2x2).
#define AROW  160
#define S_A   0
// bf16x3 layout
#define S_BHI 10240
#define S_BLO 18432
#define STGB  26624
#define SMEM_B3 (2 * STGB)         // 53248 B
// fp16 layout
#define S_BH  10240
#define STGH  18432
#define SMEM_H2 (2 * STGH)         // 36864 B
#define SMEM_DYN SMEM_B3           // vq kernel hosts both paths

// ---------------- bf16x3 core (qo GEMM) -------------------------------------
__device__ __forceinline__ void gemm_core_b3(
    const float* __restrict__ A,
    const __nv_bfloat16* __restrict__ BtHi,
    const __nv_bfloat16* __restrict__ BtLo,
    const float* __restrict__ bias,
    float* __restrict__ C, int M, int N, int bx, int by, char* sp)
{
    const uint32_t s0 = smem_u32(sp);
    const int tid  = threadIdx.x;
    const int wid  = tid >> 5;
    const int lane = tid & 31;
    const int wm   = wid >> 1;
    const int wn   = wid & 1;
    const int row0 = by * 64;
    const int col0 = bx * 128;

    const int q   = lane >> 2;
    const int t2  = (lane & 3) * 2;
    const int lrB = (lane & 7) + (lane >> 4) * 8;
    const int lkB = ((lane >> 3) & 1) * 8;

    float acc[2][8][4];
#pragma unroll
    for (int mt = 0; mt < 2; ++mt)
#pragma unroll
        for (int nt = 0; nt < 8; ++nt)
#pragma unroll
            for (int i = 0; i < 4; ++i) acc[mt][nt][i] = 0.f;

    auto load_kb = [&](int kb, int st) {
        const uint32_t sb = s0 + st * STGB;
#pragma unroll
        for (int it = 0; it < 4; ++it) {
            const int chunk = it * 128 + tid;
            const int row = chunk >> 3, c = chunk & 7;
            const int gr  = row0 + row;
            const int vr  = (gr < M) ? gr : 0;
            cp16(sb + S_A + row * AROW + c * 16,
                 A + (size_t)vr * KDIM + kb * 32 + c * 4);
        }
#pragma unroll
        for (int it = 0; it < 8; ++it) {
            const int chunk = it * 128 + tid;
            const int half = chunk >> 9;
            const int rc = chunk & 511;
            const int r = rc >> 2, c = rc & 3;
            const int csw = c ^ ((r >> 1) & 3);
            const __nv_bfloat16* src = (half ? BtLo : BtHi)
                                     + (size_t)(col0 + r) * KDIM + kb * 32 + c * 8;
            cp16(sb + (half ? S_BLO : S_BHI) + r * 64 + csw * 16, src);
        }
    };

    load_kb(0, 0);
    CP_COMMIT();

    int s = 0;
    for (int kb = 0; kb < 8; ++kb) {
        if (kb < 7) {
            load_kb(kb + 1, s ^ 1);
            CP_COMMIT();
            CP_WAIT(1);
        } else {
            CP_WAIT(0);
        }
        __syncthreads();

        const char*    spA = sp + s * STGB + S_A;
        const uint32_t sbB = s0 + s * STGB;

#pragma unroll
        for (int ks = 0; ks < 2; ++ks) {
            const int k0 = ks * 16;
            uint32_t ahi[2][4], alo[2][4];
#pragma unroll
            for (int mt = 0; mt < 2; ++mt) {
                const int rb = wm * 32 + mt * 16 + q;
#pragma unroll
                for (int i = 0; i < 4; ++i) {
                    const int r = rb + (i & 1) * 8;
                    const int k = k0 + t2 + (i >> 1) * 8;
                    const float2 f = *(const float2*)(spA + r * AROW + k * 4);
                    __nv_bfloat162 h2 = __floats2bfloat162_rn(f.x, f.y);
                    const uint32_t h = *reinterpret_cast<uint32_t*>(&h2);
                    const float g0 = __uint_as_float(h << 16);
                    const float g1 = __uint_as_float(h & 0xFFFF0000u);
                    __nv_bfloat162 l2 = __floats2bfloat162_rn(f.x - g0, f.y - g1);
                    ahi[mt][i] = h;
                    alo[mt][i] = *reinterpret_cast<uint32_t*>(&l2);
                }
            }
            const int ck = (k0 + lkB) >> 3;
#pragma unroll
            for (int np = 0; np < 4; ++np) {
                const int n = wn * 64 + np * 16 + lrB;
                const uint32_t boff = (uint32_t)(n * 64
                                      + ((ck ^ ((n >> 1) & 3)) << 4));
                uint32_t bh[4], bl[4];
                ldsm_x4(bh, sbB + S_BHI + boff);
                ldsm_x4(bl, sbB + S_BLO + boff);
#pragma unroll
                for (int mt = 0; mt < 2; ++mt) {
#pragma unroll
                    for (int h2 = 0; h2 < 2; ++h2) {
                        float* c = acc[mt][np * 2 + h2];
                        mma_bf16(c, ahi[mt], bh + h2 * 2);
                        mma_bf16(c, ahi[mt], bl + h2 * 2);
                        mma_bf16(c, alo[mt], bh + h2 * 2);
                    }
                }
            }
        }
        __syncthreads();
        s ^= 1;
    }

    const int n2 = (lane & 3) * 2;
#pragma unroll
    for (int mt = 0; mt < 2; ++mt) {
        const int mbase = row0 + wm * 32 + mt * 16 + q;
#pragma unroll
        for (int nt = 0; nt < 8; ++nt) {
            const int gc = col0 + wn * 64 + nt * 8 + n2;
            const float bx2 = bias[gc], by2 = bias[gc + 1];
            const float* c = acc[mt][nt];
#pragma unroll
            for (int half = 0; half < 2; ++half) {
                const int m = mbase + half * 8;
                if (m < M)
                    *(float2*)(C + (size_t)m * N + gc) =
                        make_float2(c[half * 2 + 0] + bx2,
                                    c[half * 2 + 1] + by2);
            }
        }
    }
}

// ---------------- fp16 single-term core (val / out GEMMs) -------------------
// C = fp16(A) * Bh^T ; one mma term per fragment pair.
template <typename OutT, bool HSPLIT>
__device__ __forceinline__ void gemm_core_h1(
    const float* __restrict__ A,
    const __half* __restrict__ Bt,
    const float* __restrict__ bias,
    OutT* __restrict__ C, int M, int N, int bx, int by, char* sp)
{
    const uint32_t s0 = smem_u32(sp);
    const int tid  = threadIdx.x;
    const int wid  = tid >> 5;
    const int lane = tid & 31;
    const int wm   = wid >> 1;
    const int wn   = wid & 1;
    const int row0 = by * 64;
    const int col0 = bx * 128;

    const int q   = lane >> 2;
    const int t2  = (lane & 3) * 2;
    const int lrB = (lane & 7) + (lane >> 4) * 8;
    const int lkB = ((lane >> 3) & 1) * 8;

    float acc[2][8][4];
#pragma unroll
    for (int mt = 0; mt < 2; ++mt)
#pragma unroll
        for (int nt = 0; nt < 8; ++nt)
#pragma unroll
            for (int i = 0; i < 4; ++i) acc[mt][nt][i] = 0.f;

    auto load_kb = [&](int kb, int st) {
        const uint32_t sb = s0 + st * STGH;
#pragma unroll
        for (int it = 0; it < 4; ++it) {
            const int chunk = it * 128 + tid;
            const int row = chunk >> 3, c = chunk & 7;
            const int gr  = row0 + row;
            const int vr  = (gr < M) ? gr : 0;
            cp16(sb + S_A + row * AROW + c * 16,
                 A + (size_t)vr * KDIM + kb * 32 + c * 4);
        }
#pragma unroll
        for (int it = 0; it < 4; ++it) {
            const int chunk = it * 128 + tid;
            const int r = chunk >> 2, c = chunk & 3;
            const int csw = c ^ ((r >> 1) & 3);
            cp16(sb + S_BH + r * 64 + csw * 16,
                 Bt + (size_t)(col0 + r) * KDIM + kb * 32 + c * 8);
        }
    };

    load_kb(0, 0);
    CP_COMMIT();

    int s = 0;
    for (int kb = 0; kb < 8; ++kb) {
        if (kb < 7) {
            load_kb(kb + 1, s ^ 1);
            CP_COMMIT();
            CP_WAIT(1);
        } else {
            CP_WAIT(0);
        }
        __syncthreads();

        const char*    spA = sp + s * STGH + S_A;
        const uint32_t sbB = s0 + s * STGH;

#pragma unroll
        for (int ks = 0; ks < 2; ++ks) {
            const int k0 = ks * 16;
            uint32_t ah[2][4];
#pragma unroll
            for (int mt = 0; mt < 2; ++mt) {
                const int rb = wm * 32 + mt * 16 + q;
#pragma unroll
                for (int i = 0; i < 4; ++i) {
                    const int r = rb + (i & 1) * 8;
                    const int k = k0 + t2 + (i >> 1) * 8;
                    const float2 f = *(const float2*)(spA + r * AROW + k * 4);
                    const __half2 h2 = __floats2half2_rn(f.x, f.y);
                    ah[mt][i] = *reinterpret_cast<const uint32_t*>(&h2);
                }
            }
            const int ck = (k0 + lkB) >> 3;
#pragma unroll
            for (int np = 0; np < 4; ++np) {
                const int n = wn * 64 + np * 16 + lrB;
                const uint32_t boff = (uint32_t)(n * 64
                                      + ((ck ^ ((n >> 1) & 3)) << 4));
                uint32_t bh[4];
                ldsm_x4(bh, sbB + S_BH + boff);
#pragma unroll
                for (int mt = 0; mt < 2; ++mt) {
#pragma unroll
                    for (int h2 = 0; h2 < 2; ++h2)
                        mma_f16(acc[mt][np * 2 + h2], ah[mt], bh + h2 * 2);
                }
            }
        }
        __syncthreads();
        s ^= 1;
    }

    const int n2 = (lane & 3) * 2;
#pragma unroll
    for (int mt = 0; mt < 2; ++mt) {
        const int mbase = row0 + wm * 32 + mt * 16 + q;
#pragma unroll
        for (int nt = 0; nt < 8; ++nt) {
            const int gc = col0 + wn * 64 + nt * 8 + n2;
            const float bx2 = bias[gc], by2 = bias[gc + 1];
            const float* c = acc[mt][nt];
#pragma unroll
            for (int half = 0; half < 2; ++half) {
                const int m = mbase + half * 8;
                if (m < M) {
                    if constexpr (HSPLIT) {
                        const int b   = m / LTOT;
                        const int loc = m - b * LTOT;
                        const int hh  = gc >> 5;
                        const int ch  = gc & 31;
                        const size_t addr =
                            (((size_t)(b * NH + hh) * LTOT + loc) << 5) + ch;
                        *(__half2*)((__half*)C + addr) =
                            __floats2half2_rn(c[half * 2 + 0] + bx2,
                                              c[half * 2 + 1] + by2);
                    } else {
                        *(float2*)((float*)C + (size_t)m * N + gc) =
                            make_float2(c[half * 2 + 0] + bx2,
                                        c[half * 2 + 1] + by2);
                    }
                }
            }
        }
    }
}

// fused val + qo GEMMs in one launch (linearized grid)
#define NVB (2 * 1834)            // val blocks: x=2, y=1834
__global__ __launch_bounds__(128, 4)
void gemm_vq_kernel(const float* __restrict__ Aval,
                    const float* __restrict__ Aqry,
                    const __half* __restrict__ w16,
                    const __nv_bfloat16* __restrict__ wth,
                    const __nv_bfloat16* __restrict__ wtl,
                    const float* __restrict__ bval,
                    const float* __restrict__ bqo,
                    __half* __restrict__ Cval, float* __restrict__ Cqo)
{
    extern __shared__ __align__(16) char sp[];
    const int bid = blockIdx.x;
    if (bid < NVB) {
        gemm_core_h1<__half, true>(Aval, w16 + (size_t)W16_VAL * 256,
                                   bval, Cval, MV, 256, bid & 1, bid >> 1, sp);
    } else {
        const int r = bid - NVB;
        gemm_core_b3(Aqry, wth, wtl, bqo, Cqo, MQ, 768, r % 6, r / 6, sp);
    }
}

__global__ __launch_bounds__(128, 4)
void gemm_out_kernel(const float* __restrict__ A,
                     const __half* __restrict__ w16,
                     const float* __restrict__ bias,
                     float* __restrict__ C)
{
    extern __shared__ __align__(16) char sp[];
    gemm_core_h1<float, false>(A, w16 + (size_t)W16_OUT * 256,
                               bias, C, MQ, 256, blockIdx.x, blockIdx.y, sp);
}

// ---------------- deformable sampling core --------------------------------
// g_v is head-split: [b][head][loc][32ch fp16] -> 64 B per (head,loc).
__global__ __launch_bounds__(256)
void msda_sample_kernel(const float* __restrict__ refp)
{
    __shared__ float2 st[NH][4][36];     // [head][corner][point(+pad)]

    const int bq   = blockIdx.x;
    const int lane = threadIdx.x;
    const int h    = threadIdx.y;
    const int b    = bq >> 12;

    const float aval = g_qo[(size_t)bq * 768 + h * 32 + lane];
    float mx = aval;
#pragma unroll
    for (int s = 16; s; s >>= 1) mx = fmaxf(mx, __shfl_xor_sync(0xffffffffu, mx, s));
    const float e = __expf(aval - mx);
    float sm = e;
#pragma unroll
    for (int s = 16; s; s >>= 1) sm += __shfl_xor_sync(0xffffffffu, sm, s);
    const float aw = e / sm;

    {
        const int j  = lane;
        const int lv = j >> 3;
        const int Wl = cWL[lv], Hl = cHL[lv];

        const float2 o2 = *(const float2*)(g_qo + (size_t)bq * 768 + 256
                                           + h * 64 + j * 2);
        const float rx = refp[(size_t)bq * 8 + lv * 2];
        const float ry = refp[(size_t)bq * 8 + lv * 2 + 1];

        const float locx = rx + o2.x * cIW[lv];
        const float locy = ry + o2.y * cIH[lv];
        const float gx = 2.f * locx - 1.f;
        const float gy = 2.f * locy - 1.f;
        const float x = (gx + 1.f) * ((float)Wl * 0.5f) - 0.5f;
        const float y = (gy + 1.f) * ((float)Hl * 0.5f) - 0.5f;

        const float xf = floorf(x), yf = floorf(y);
        const float wx = x - xf,    wy = y - yf;
        const int x0 = (int)xf, y0 = (int)yf;
        const int x1 = x0 + 1,  y1 = y0 + 1;

        const bool vx0 = (x0 >= 0) && (x0 < Wl);
        const bool vx1 = (x1 >= 0) && (x1 < Wl);
        const bool vy0 = (y0 >= 0) && (y0 < Hl);
        const bool vy1 = (y1 >= 0) && (y1 < Hl);

        const int xA = min(max(x0, 0), Wl - 1);
        const int xB = min(max(x1, 0), Wl - 1);
        const int yA = min(max(y0, 0), Hl - 1);
        const int yB = min(max(y1, 0), Hl - 1);

        const int base = cST[lv];
        const int off00 = (base + yA * Wl + xA) << 6;
        const int off10 = (base + yA * Wl + xB) << 6;
        const int off01 = (base + yB * Wl + xA) << 6;
        const int off11 = (base + yB * Wl + xB) << 6;

        const float w00 = (vx0 && vy0) ? aw * (1.f - wx) * (1.f - wy) : 0.f;
        const float w10 = (vx1 && vy0) ? aw * wx         * (1.f - wy) : 0.f;
        const float w01 = (vx0 && vy1) ? aw * (1.f - wx) * wy         : 0.f;
        const float w11 = (vx1 && vy1) ? aw * wx         * wy         : 0.f;

        st[h][0][j] = make_float2(__int_as_float(off00), w00);
        st[h][1][j] = make_float2(__int_as_float(off10), w10);
        st[h][2][j] = make_float2(__int_as_float(off01), w01);
        st[h][3][j] = make_float2(__int_as_float(off11), w11);
    }
    __syncwarp();

    const int g  = lane >> 3;
    const int cq = lane & 7;
    const char* vb = (const char*)(g_v
        + (((size_t)(b * NH + h) * LTOT) << 5) + cq * 4);
    const float2* owrow = st[h][g];

    float4 acc = make_float4(0.f, 0.f, 0.f, 0.f);
#pragma unroll 4
    for (int p = 0; p < 32; p += 2) {
        const float4 ow2 = *(const float4*)(owrow + p);
        const uint2 ua = *(const uint2*)(vb + __float_as_int(ow2.x));
        const uint2 ub = *(const uint2*)(vb + __float_as_int(ow2.z));
        const float2 a01 = __half22float2(*(const __half2*)&ua.x);
        const float2 a23 = __half22float2(*(const __half2*)&ua.y);
        const float2 b01 = __half22float2(*(const __half2*)&ub.x);
        const float2 b23 = __half22float2(*(const __half2*)&ub.y);
        acc.x = fmaf(ow2.y, a01.x, acc.x);
        acc.y = fmaf(ow2.y, a01.y, acc.y);
        acc.z = fmaf(ow2.y, a23.x, acc.z);
        acc.w = fmaf(ow2.y, a23.y, acc.w);
        acc.x = fmaf(ow2.w, b01.x, acc.x);
        acc.y = fmaf(ow2.w, b01.y, acc.y);
        acc.z = fmaf(ow2.w, b23.x, acc.z);
        acc.w = fmaf(ow2.w, b23.y, acc.w);
    }
#pragma unroll
    for (int s = 8; s <= 16; s <<= 1) {
        acc.x += __shfl_xor_sync(0xffffffffu, acc.x, s);
        acc.y += __shfl_xor_sync(0xffffffffu, acc.y, s);
        acc.z += __shfl_xor_sync(0xffffffffu, acc.z, s);
        acc.w += __shfl_xor_sync(0xffffffffu, acc.w, s);
    }
    if (g == 0)
        *(float4*)(g_tmp + (size_t)bq * EMB + h * 32 + cq * 4) = acc;
}

// ---------------- launch ---------------------------------------------------
extern "C" void kernel_launch(void* const* d_in, const int* in_sizes, int n_in,
                              void* d_out, int out_size)
{
    const float* query  = (const float*)d_in[0];
    const float* value  = (const float*)d_in[1];
    const float* refp   = (const float*)d_in[2];
    const float* W_off  = (const float*)d_in[4];
    const float* b_off  = (const float*)d_in[5];
    const float* W_attn = (const float*)d_in[6];
    const float* b_attn = (const float*)d_in[7];
    const float* W_val  = (const float*)d_in[8];
    const float* b_val  = (const float*)d_in[9];
    const float* W_out  = (const float*)d_in[10];
    const float* b_out  = (const float*)d_in[11];
    float* out = (float*)d_out;

    float *gqo, *gtmp, *gbqo;
    __half *gv, *gw16;
    __nv_bfloat16 *wth, *wtl;
    cudaGetSymbolAddress((void**)&gv,   g_v);
    cudaGetSymbolAddress((void**)&gqo,  g_qo);
    cudaGetSymbolAddress((void**)&gtmp, g_tmp);
    cudaGetSymbolAddress((void**)&gbqo, g_bqo);
    cudaGetSymbolAddress((void**)&gw16, g_w16);
    cudaGetSymbolAddress((void**)&wth,  g_wt_hi);
    cudaGetSymbolAddress((void**)&wtl,  g_wt_lo);

    cudaFuncSetAttribute(gemm_vq_kernel,
                         cudaFuncAttributeMaxDynamicSharedMemorySize, SMEM_DYN);
    cudaFuncSetAttribute(gemm_out_kernel,
                         cudaFuncAttributeMaxDynamicSharedMemorySize, SMEM_H2);

    // 0) weight prep
    prep_weights<<<1280, 256>>>(W_val, W_attn, W_off, W_out, b_attn, b_off);

    // 1) fused: value projection (fp16 single-term, head-split) -> g_v + qo -> g_qo
    gemm_vq_kernel<<<NVB + 6 * (MQ / 64), 128, SMEM_DYN>>>(
        value, query, gw16, wth, wtl, b_val, gbqo, gv, gqo);

    // 2) softmax + bilinear sampling -> g_tmp
    msda_sample_kernel<<<MQ, dim3(32, 8)>>>(refp);

    // 3) output projection (fp16 single-term) -> d_out
    gemm_out_kernel<<<dim3(2, MQ / 64), 128, SMEM_H2>>>(
        gtmp, gw16, b_out, out);
}